// round 7
// baseline (speedup 1.0000x reference)
#include <cuda_runtime.h>
#include <cuda_fp16.h>
#include <math.h>
#include <stdint.h>

// ---------------- problem constants ----------------
#define NSAMP   1024
#define NCLS    9
#define PRE_K   512
#define DETS    100
#define IMGW    640.0f
#define IMGH    384.0f

#define O_EMB   ((size_t)0)
#define O_CLS   ((size_t)51380224)
#define O_REG   ((size_t)51389440)
#define O_BOX   ((size_t)51426304)
#define O_SCO   ((size_t)51427104)
#define O_LAB   ((size_t)51427304)
#define O_VAL   ((size_t)51427504)

// ---------------- scratch (device globals; no allocation) ----------------
// fp16 hi/lo split images, rows padded to 56 halves (112B); pads stay zero
__device__ __half g_x16 [(size_t)1024*512*56];
__device__ __half g_x16l[(size_t)1024*512*56];
__device__ __half g_h16 [(size_t)1024*1024*56];
__device__ __half g_h16l[(size_t)1024*1024*56];
__device__ __half g_w1h [(size_t)1024*4608];      // w1 hi [co][ci*9+tap]
__device__ __half g_w1l [(size_t)1024*4608];      // w1 lo
__device__ __half g_wbh [(size_t)1024*9728];      // [w2|wd] hi [co][kk]
__device__ __half g_wbl [(size_t)1024*9728];      // [w2|wd] lo
__device__ float  g_flat[(size_t)NSAMP*1024];
__device__ float  g_cls[NSAMP*NCLS];
__device__ float  g_reg[NSAMP*NCLS*4];
__device__ float  g_boxes[NSAMP*NCLS*4];
__device__ float  g_scores[NSAMP*NCLS];

// ================= PTX helpers (all sm_80-generic) =================
__device__ __forceinline__ uint32_t smem_u32(const void* p) {
    uint32_t a;
    asm("{ .reg .u64 t; cvta.to.shared.u64 t, %1; cvt.u32.u64 %0, t; }" : "=r"(a) : "l"(p));
    return a;
}
__device__ __forceinline__ void cp_async16(uint32_t dst, const void* src) {
    asm volatile("cp.async.cg.shared.global [%0], [%1], 16;" :: "r"(dst), "l"(src) : "memory");
}
#define CP_COMMIT() asm volatile("cp.async.commit_group;" ::: "memory")
#define CP_WAIT0()  asm volatile("cp.async.wait_group 0;" ::: "memory")

__device__ __forceinline__ uint32_t lds32(uint32_t a) {
    uint32_t v; asm volatile("ld.shared.u32 %0, [%1];" : "=r"(v) : "r"(a)); return v;
}
__device__ __forceinline__ void sts32(uint32_t a, uint32_t v) {
    asm volatile("st.shared.u32 [%0], %1;" :: "r"(a), "r"(v) : "memory");
}
__device__ __forceinline__ void ldm_x4(uint32_t* r, uint32_t a) {
    asm volatile("ldmatrix.sync.aligned.m8n8.x4.shared.b16 {%0,%1,%2,%3}, [%4];"
        : "=r"(r[0]), "=r"(r[1]), "=r"(r[2]), "=r"(r[3]) : "r"(a));
}
__device__ __forceinline__ void ldm_x4t(uint32_t* r, uint32_t a) {
    asm volatile("ldmatrix.sync.aligned.m8n8.x4.trans.shared.b16 {%0,%1,%2,%3}, [%4];"
        : "=r"(r[0]), "=r"(r[1]), "=r"(r[2]), "=r"(r[3]) : "r"(a));
}
__device__ __forceinline__ void mma16816(float* c, const uint32_t* a, uint32_t b0, uint32_t b1) {
    asm volatile(
        "mma.sync.aligned.m16n8k16.row.col.f32.f16.f16.f32 "
        "{%0,%1,%2,%3}, {%4,%5,%6,%7}, {%8,%9}, {%0,%1,%2,%3};"
        : "+f"(c[0]), "+f"(c[1]), "+f"(c[2]), "+f"(c[3])
        : "r"(a[0]), "r"(a[1]), "r"(a[2]), "r"(a[3]), "r"(b0), "r"(b1));
}

// ---------------- convert kernels (hi/lo split) ----------------
__global__ void cvt_x16(const float* __restrict__ x) {
    size_t i = (size_t)blockIdx.x * 256 + threadIdx.x;
    if (i >= (size_t)1024*512*56) return;
    int p = (int)(i % 56);
    size_t row = i / 56;
    float v = (p < 49) ? x[row * 49 + p] : 0.f;
    __half hh = __float2half(v);
    g_x16[i]  = hh;
    g_x16l[i] = __float2half(v - __half2float(hh));
}
__global__ void cvt_w1h(const float* __restrict__ w) {
    size_t i = (size_t)blockIdx.x * 256 + threadIdx.x;
    if (i >= (size_t)1024*4608) return;
    float v = w[i];
    __half hh = __float2half(v);
    g_w1h[i] = hh;
    g_w1l[i] = __float2half(v - __half2float(hh));
}
__global__ void cvt_wbh(const float* __restrict__ w2, const float* __restrict__ wd) {
    size_t i = (size_t)blockIdx.x * 256 + threadIdx.x;
    if (i >= (size_t)1024*9728) return;
    int co = (int)(i / 9728);
    int kk = (int)(i - (size_t)co * 9728);
    float v = (kk < 9216) ? w2[(size_t)co * 9216 + kk] : wd[(size_t)co * 512 + (kk - 9216)];
    __half hh = __float2half(v);
    g_wbh[i] = hh;
    g_wbl[i] = __float2half(v - __half2float(hh));
}

// ---------------- smem layout (single-buffered, hi+lo) ----------------
// A^T: [144 kk][136 halves] (272B rows), hi and lo
// B  : [128 co][152 halves] (304B rows), hi and lo
// img: [128 rows][36 words] (144B rows: 4 guard + 28 data + 4 guard), hi and lo
#define AST  272u
#define BST  304u
#define AH_OFF 0u
#define AL_OFF 39168u
#define BH_OFF 78336u
#define BL_OFF 117248u
#define IH_OFF 156160u
#define IL_OFF 174592u
#define MTAB_OFF 193024u
#define GSMEM    194048

__device__ __forceinline__ void mma_tiles(uint32_t As, uint32_t Bs, int ksteps,
                                          int lane, int wm, int wn,
                                          float (&acc)[4][4][4]) {
    uint32_t aBase = As + ((lane & 7) + ((lane >> 4) & 1) * 8) * AST
                        + (uint32_t)(wm * 64 + ((lane >> 3) & 1) * 8) * 2u;
    uint32_t bBase = Bs + (uint32_t)(wn * 32 + (lane & 15)) * BST + ((lane >> 4) & 1) * 16u;
    for (int ks = 0; ks < ksteps; ks++) {
        uint32_t A[4][4];
        #pragma unroll
        for (int i = 0; i < 4; i++) ldm_x4t(A[i], aBase + (uint32_t)ks * (16u * AST) + i * 32u);
        uint32_t Q0[4], Q1[4];
        ldm_x4(Q0, bBase + (uint32_t)ks * 32u);
        ldm_x4(Q1, bBase + (uint32_t)ks * 32u + 16u * BST);
        #pragma unroll
        for (int i = 0; i < 4; i++) {
            mma16816(acc[i][0], A[i], Q0[0], Q0[2]);
            mma16816(acc[i][1], A[i], Q0[1], Q0[3]);
            mma16816(acc[i][2], A[i], Q1[0], Q1[2]);
            mma16816(acc[i][3], A[i], Q1[1], Q1[3]);
        }
    }
}

// P=1: conv1 (x -> relu -> h hi/lo).  P=2: conv2 + 1x1 shortcut (-> relu -> d_out)
template<int P>
__global__ void __launch_bounds__(256, 1) conv_gemm(float* __restrict__ d_out) {
    extern __shared__ char smem[];
    const uint32_t sb = smem_u32(smem);
    const int tid  = threadIdx.x;
    const int lane = tid & 31;
    const int wm = (tid >> 5) >> 2, wn = (tid >> 5) & 3;
    const int nt = blockIdx.x;            // 8 n-tiles (128 couts)
    const int mt = blockIdx.y;            // 512 m-tiles (2 samples)
    const int n0 = mt * 2;

    const int KT          = (P == 1) ? 4608 : 9728;
    const int mainStages  = (P == 1) ? 32 : 64;
    const int totalStages = (P == 1) ? 32 : 72;     // P2: +8 shortcut stages (K=64)
    const int CI          = (P == 1) ? 512 : 1024;

    // ---- boundary mask table ----
    if (tid < 225) {
        int off = tid / 25, i = tid - (tid / 25) * 25;
        int ky = off / 3, kx = off - ky * 3;
        uint32_t m = 0;
        #pragma unroll
        for (int h = 0; h < 2; h++) {
            int p = 2 * i + h;
            if (p < 49) {
                int y = p / 7, x = p - (p / 7) * 7;
                int yy = y + ky - 1, xx = x + kx - 1;
                if (yy >= 0 && yy < 7 && xx >= 0 && xx < 7) m |= 0xFFFFu << (16 * h);
            }
        }
        sts32(sb + MTAB_OFF + (uint32_t)tid * 4u, m);
    }

    // one precision's loads for stage s into (bo, io)
    auto issueLoads = [&](int s, const __half* wsrc, const __half* isrc,
                          const __half* xsrc, uint32_t bo, uint32_t io) {
        if (s >= totalStages) return;
        if (s < mainStages) {
            // B: 128 rows x 288B; 2 threads/row x 9 chunks
            {
                int r = tid >> 1, h = tid & 1;
                const char* wrow = (const char*)wsrc +
                    ((size_t)(nt * 128 + r) * KT + (size_t)s * 144 + h * 72) * 2;
                uint32_t bd = sb + bo + (uint32_t)r * BST + (uint32_t)h * 144u;
                #pragma unroll
                for (int q = 0; q < 9; q++) cp_async16(bd + q * 16u, wrow + q * 16);
            }
            // img: 32 rows (16 ci x 2 samples) x 7 chunks of 16B at word 4
            int ci0 = s * 16;
            for (int i = tid; i < 224; i += 256) {
                int r = i / 7, c = i - (i / 7) * 7;
                int n_l = r >> 4, ci = ci0 + (r & 15);
                const char* src = (const char*)isrc +
                    ((size_t)(n0 + n_l) * CI + ci) * 56 * 2 + c * 16;
                cp_async16(sb + io + (uint32_t)r * 144u + 16u + (uint32_t)c * 16u, src);
            }
            // zero guard words 0-3 and 32-35 of rows 0..31
            {
                int r = tid >> 3, j = tid & 7;
                int w = (j < 4) ? j : (28 + j);
                if (r < 32) sts32(sb + io + (uint32_t)r * 144u + (uint32_t)w * 4u, 0u);
            }
        } else {
            int ss = s - mainStages;
            // B: 128 rows x 128B (shortcut cols 9216 + ss*64)
            {
                int r = tid >> 1, h = tid & 1;
                const char* wrow = (const char*)wsrc +
                    ((size_t)(nt * 128 + r) * KT + 9216 + (size_t)ss * 64) * 2 + h * 64;
                uint32_t bd = sb + bo + (uint32_t)r * BST + (uint32_t)h * 64u;
                #pragma unroll
                for (int q = 0; q < 4; q++) cp_async16(bd + q * 16u, wrow + q * 16);
            }
            // img: 128 rows (64 ci x 2 samples) x 7 chunks from x
            int ci0 = ss * 64;
            for (int i = tid; i < 896; i += 256) {
                int r = i / 7, c = i - (i / 7) * 7;
                int n_l = r >> 6, ci = ci0 + (r & 63);
                const char* src = (const char*)xsrc +
                    ((size_t)(n0 + n_l) * 512 + ci) * 56 * 2 + c * 16;
                cp_async16(sb + io + (uint32_t)r * 144u + 16u + (uint32_t)c * 16u, src);
            }
        }
    };

    auto buildA = [&](int s, uint32_t io, uint32_t ao) {
        uint32_t ibase = sb + io;
        uint32_t abase = sb + ao;
        if (s < mainStages) {
            // half-shifted copies in rows 32..63
            for (int i = tid; i < 32 * 34; i += 256) {
                int r = i / 34, w = i - (i / 34) * 34;
                uint32_t lo = lds32(ibase + (uint32_t)r * 144u + (uint32_t)w * 4u);
                uint32_t hi = lds32(ibase + (uint32_t)r * 144u + (uint32_t)w * 4u + 4u);
                sts32(ibase + (uint32_t)(32 + r) * 144u + (uint32_t)w * 4u,
                      __funnelshift_r(lo, hi, 16));
            }
            __syncthreads();
            for (int t = tid; t < 288; t += 256) {
                int kk = t >> 1, n_l = t & 1;
                int ci_l = kk / 9, off = kk - ci_l * 9;
                int ky = off / 3, kx = off - ky * 3;
                int del = (ky - 1) * 7 + (kx - 1);
                int c  = del & 1;
                int ws = (del - c) >> 1;
                uint32_t srcw = ibase + (uint32_t)(c * 32 + n_l * 16 + ci_l) * 144u
                              + (uint32_t)(4 + ws) * 4u;
                uint32_t mrow = sb + MTAB_OFF + (uint32_t)(off * 25) * 4u;
                uint32_t dstw = abase + (uint32_t)kk * AST + (uint32_t)n_l * 128u;
                #pragma unroll
                for (int i = 0; i < 25; i++)
                    sts32(dstw + i * 4u, lds32(srcw + i * 4u) & lds32(mrow + i * 4u));
                #pragma unroll
                for (int i = 25; i < 32; i++) sts32(dstw + i * 4u, 0u);
            }
        } else {
            __syncthreads();   // uniform barrier count with main path
            if (tid < 128) {
                int kk = tid >> 1, n_l = tid & 1;
                uint32_t srcw = ibase + (uint32_t)(n_l * 64 + kk) * 144u + 16u;
                uint32_t dstw = abase + (uint32_t)kk * AST + (uint32_t)n_l * 128u;
                #pragma unroll
                for (int i = 0; i < 25; i++) sts32(dstw + i * 4u, lds32(srcw + i * 4u));
                #pragma unroll
                for (int i = 25; i < 32; i++) sts32(dstw + i * 4u, 0u);
            }
        }
    };

    const __half* WH = (P == 1) ? g_w1h : g_wbh;
    const __half* WL = (P == 1) ? g_w1l : g_wbl;
    const __half* IHsrc = (P == 1) ? g_x16  : g_h16;
    const __half* ILsrc = (P == 1) ? g_x16l : g_h16l;

    float acc[4][4][4];
    #pragma unroll
    for (int i = 0; i < 4; i++)
        #pragma unroll
        for (int j = 0; j < 4; j++) {
            acc[i][j][0] = 0.f; acc[i][j][1] = 0.f; acc[i][j][2] = 0.f; acc[i][j][3] = 0.f;
        }

    issueLoads(0, WH, IHsrc, g_x16, BH_OFF, IH_OFF); CP_COMMIT();

    for (int s = 0; s < totalStages; s++) {
        const int ks = (s < mainStages) ? 9 : 4;
        CP_WAIT0();
        __syncthreads();                 // hi(s) data visible (and mask table on s==0)
        // lo loads overlap with hi build + AhBh pass
        issueLoads(s, WL, ILsrc, g_x16l, BL_OFF, IL_OFF); CP_COMMIT();
        buildA(s, IH_OFF, AH_OFF);       // internal sync
        __syncthreads();                 // Ah complete
        mma_tiles(sb + AH_OFF, sb + BH_OFF, ks, lane, wm, wn, acc);
        CP_WAIT0();
        __syncthreads();                 // lo(s) data visible
        buildA(s, IL_OFF, AL_OFF);       // internal sync
        __syncthreads();                 // Al complete
        mma_tiles(sb + AL_OFF, sb + BH_OFF, ks, lane, wm, wn, acc);
        mma_tiles(sb + AH_OFF, sb + BL_OFF, ks, lane, wm, wn, acc);
        __syncthreads();                 // all stage-s reads done before refill
        issueLoads(s + 1, WH, IHsrc, g_x16, BH_OFF, IH_OFF); CP_COMMIT();
    }

    // ---- epilogue: stage through smem [128 co][132 m] floats ----
    float* sf = (float*)smem;
    #pragma unroll
    for (int i = 0; i < 4; i++) {
        #pragma unroll
        for (int j = 0; j < 4; j++) {
            int m  = wm * 64 + i * 16 + (lane >> 2);
            int co = wn * 32 + j * 8 + ((lane & 3) << 1);
            sf[co * 132 + m]           = fmaxf(acc[i][j][0], 0.f);
            sf[(co + 1) * 132 + m]     = fmaxf(acc[i][j][1], 0.f);
            sf[co * 132 + m + 8]       = fmaxf(acc[i][j][2], 0.f);
            sf[(co + 1) * 132 + m + 8] = fmaxf(acc[i][j][3], 0.f);
        }
    }
    __syncthreads();
    for (int idx = tid; idx < 128 * 98; idx += 256) {
        int co_l = idx / 98;
        int mm   = idx - co_l * 98;
        int nsel = mm >= 49;
        int p    = mm - nsel * 49;
        float v  = sf[co_l * 132 + nsel * 64 + p];
        int co_g = nt * 128 + co_l;
        int n    = n0 + nsel;
        if (P == 1) {
            size_t o = ((size_t)(n * 1024 + co_g)) * 56 + p;
            __half hh = __float2half(v);
            g_h16[o]  = hh;
            g_h16l[o] = __float2half(v - __half2float(hh));
        } else {
            d_out[O_EMB + ((size_t)(n * 1024 + co_g)) * 49 + p] = v;
        }
    }
}

// ---------------- avg pool ----------------
__global__ void flat_kernel(const float* __restrict__ emb) {
    int n = blockIdx.x;
    for (int co = threadIdx.x; co < 1024; co += 256) {
        const float* e = emb + ((size_t)n * 1024 + co) * 49;
        float s = 0.f;
        #pragma unroll
        for (int p = 0; p < 49; p++) s += e[p];
        g_flat[(size_t)n * 1024 + co] = s / 49.0f;
    }
}

// ---------------- head GEMMs ----------------
__global__ void head_kernel(const float* __restrict__ cls_w, const float* __restrict__ cls_b,
                            const float* __restrict__ reg_w, const float* __restrict__ reg_b,
                            float* __restrict__ d_out) {
    int n = blockIdx.x;
    int w = threadIdx.x >> 5, lane = threadIdx.x & 31;
    const float* f = g_flat + (size_t)n * 1024;
    for (int o = w; o < 45; o += 8) {
        const float* wr; float bias;
        if (o < NCLS) { wr = cls_w + (size_t)o * 1024; bias = cls_b[o]; }
        else          { wr = reg_w + (size_t)(o - NCLS) * 1024; bias = reg_b[o - NCLS]; }
        float acc = 0.f;
        for (int k = lane; k < 1024; k += 32) acc += f[k] * wr[k];
        #pragma unroll
        for (int d = 16; d; d >>= 1) acc += __shfl_xor_sync(0xffffffffu, acc, d);
        if (lane == 0) {
            float v = acc + bias;
            if (o < NCLS) { g_cls[n * NCLS + o] = v; d_out[O_CLS + n * NCLS + o] = v; }
            else { g_reg[n * 36 + (o - NCLS)] = v; d_out[O_REG + n * 36 + (o - NCLS)] = v; }
        }
    }
}

// ---------------- softmax + box decode + clip ----------------
__global__ void decode_kernel(const float* __restrict__ proposals) {
    int n = blockIdx.x; int lane = threadIdx.x;
    float logit = (lane < NCLS) ? g_cls[n * NCLS + lane] : -INFINITY;
    float m = logit;
    #pragma unroll
    for (int d = 16; d; d >>= 1) m = fmaxf(m, __shfl_xor_sync(0xffffffffu, m, d));
    float e = (lane < NCLS) ? expf(logit - m) : 0.f;
    float s = e;
    #pragma unroll
    for (int d = 16; d; d >>= 1) s += __shfl_xor_sync(0xffffffffu, s, d);
    if (lane < NCLS) {
        g_scores[n * NCLS + lane] = e / s;
        const float* pr = proposals + (size_t)n * 4;
        float pw = pr[2] - pr[0], ph = pr[3] - pr[1];
        float pcx = pr[0] + 0.5f * pw, pcy = pr[1] + 0.5f * ph;
        const float* rr = g_reg + n * 36 + lane * 4;
        float dx = rr[0] / 10.0f, dy = rr[1] / 10.0f;
        float dw = fminf(rr[2] / 5.0f, 4.135166556742356f);
        float dh = fminf(rr[3] / 5.0f, 4.135166556742356f);
        float ncx = dx * pw + pcx, ncy = dy * ph + pcy;
        float nw = expf(dw) * pw, nh = expf(dh) * ph;
        float b0 = fminf(fmaxf(ncx - 0.5f * nw, 0.f), IMGW);
        float b1 = fminf(fmaxf(ncy - 0.5f * nh, 0.f), IMGH);
        float b2 = fminf(fmaxf(ncx + 0.5f * nw, 0.f), IMGW);
        float b3 = fminf(fmaxf(ncy + 0.5f * nh, 0.f), IMGH);
        float* bp = g_boxes + (size_t)(n * NCLS + lane) * 4;
        bp[0] = b0; bp[1] = b1; bp[2] = b2; bp[3] = b3;
    }
}

// ---------------- per-image: filter -> sort(4096) -> NMS(512) -> top-100 ----------------
__global__ void __launch_bounds__(512) nms_kernel(float* __restrict__ d_out) {
    __shared__ float skey[4096];
    __shared__ int   sidx[4096];
    __shared__ float sbox[PRE_K * 4];
    __shared__ int   skeep[PRE_K];
    __shared__ int   swsum[16];

    int img = blockIdx.x; int tid = threadIdx.x;

    for (int j = tid; j < 4096; j += 512) {
        int p = j >> 3, c = (j & 7) + 1;
        int n = img * 512 + p;
        float s = g_scores[n * NCLS + c];
        const float* bb = g_boxes + (size_t)(n * NCLS + c) * 4;
        bool valid = (s > 0.05f) && ((bb[2] - bb[0]) >= 0.01f) && ((bb[3] - bb[1]) >= 0.01f);
        skey[j] = valid ? s : -INFINITY;
        sidx[j] = j;
    }
    __syncthreads();

    for (int k = 2; k <= 4096; k <<= 1) {
        for (int j2 = k >> 1; j2 > 0; j2 >>= 1) {
            for (int i = tid; i < 4096; i += 512) {
                int ixj = i ^ j2;
                if (ixj > i) {
                    float ka = skey[i], kb = skey[ixj];
                    int ia = sidx[i], ib = sidx[ixj];
                    bool a_first = (ka > kb) || (ka == kb && ia < ib);
                    bool up = ((i & k) == 0);
                    if (up ? !a_first : a_first) {
                        skey[i] = kb; skey[ixj] = ka;
                        sidx[i] = ib; sidx[ixj] = ia;
                    }
                }
            }
            __syncthreads();
        }
    }

    if (tid < PRE_K) {
        float s = skey[tid];
        int j = sidx[tid];
        int p = j >> 3, c = (j & 7) + 1;
        int n = img * 512 + p;
        const float* bb = g_boxes + (size_t)(n * NCLS + c) * 4;
        float off = 641.0f * (float)c;
        sbox[tid * 4 + 0] = bb[0] + off;
        sbox[tid * 4 + 1] = bb[1] + off;
        sbox[tid * 4 + 2] = bb[2] + off;
        sbox[tid * 4 + 3] = bb[3] + off;
        skeep[tid] = (s != -INFINITY) ? 1 : 0;
    }
    __syncthreads();

    for (int i = 0; i < PRE_K; i++) {
        if (skeep[i]) {
            int j = tid;
            if (j > i && skeep[j]) {
                float ax0 = sbox[i*4], ay0 = sbox[i*4+1], ax1 = sbox[i*4+2], ay1 = sbox[i*4+3];
                float bx0 = sbox[j*4], by0 = sbox[j*4+1], bx1 = sbox[j*4+2], by1 = sbox[j*4+3];
                float areaA = (ax1 - ax0) * (ay1 - ay0);
                float areaB = (bx1 - bx0) * (by1 - by0);
                float iw = fmaxf(fminf(ax1, bx1) - fmaxf(ax0, bx0), 0.f);
                float ih = fmaxf(fminf(ay1, by1) - fmaxf(ay0, by0), 0.f);
                float inter = iw * ih;
                float iou = inter / fmaxf(areaA + areaB - inter, 1e-8f);
                if (iou > 0.5f) skeep[j] = 0;
            }
        }
        __syncthreads();
    }

    int keepflag = (tid < PRE_K) ? skeep[tid] : 0;
    unsigned mask = __ballot_sync(0xffffffffu, keepflag != 0);
    int lane = tid & 31, wid = tid >> 5;
    if (lane == 0) swsum[wid] = __popc(mask);
    __syncthreads();
    int base = 0;
    for (int w = 0; w < wid; w++) base += swsum[w];
    int rank = base + __popc(mask & ((1u << lane) - 1u));

    float* dbx = d_out + O_BOX + (size_t)img * DETS * 4;
    float* dsc = d_out + O_SCO + (size_t)img * DETS;
    float* dlb = d_out + O_LAB + (size_t)img * DETS;
    float* dvl = d_out + O_VAL + (size_t)img * DETS;
    for (int i = tid; i < DETS; i += 512) {
        dbx[i*4+0] = 0.f; dbx[i*4+1] = 0.f; dbx[i*4+2] = 0.f; dbx[i*4+3] = 0.f;
        dsc[i] = 0.f; dlb[i] = 0.f; dvl[i] = 0.f;
    }
    __syncthreads();
    if (keepflag && rank < DETS) {
        int j = sidx[tid];
        int p = j >> 3, c = (j & 7) + 1;
        int n = img * 512 + p;
        const float* bb = g_boxes + (size_t)(n * NCLS + c) * 4;
        dbx[rank*4+0] = bb[0]; dbx[rank*4+1] = bb[1];
        dbx[rank*4+2] = bb[2]; dbx[rank*4+3] = bb[3];
        dsc[rank] = skey[tid];
        dlb[rank] = (float)c;
        dvl[rank] = 1.0f;
    }
}

// ---------------- launch ----------------
extern "C" void kernel_launch(void* const* d_in, const int* in_sizes, int n_in,
                              void* d_out, int out_size) {
    const float* feats     = (const float*)d_in[0];
    const float* proposals = (const float*)d_in[1];
    const float* w1        = (const float*)d_in[2];
    const float* w2        = (const float*)d_in[3];
    const float* wd        = (const float*)d_in[4];
    const float* cls_w     = (const float*)d_in[5];
    const float* cls_b     = (const float*)d_in[6];
    const float* reg_w     = (const float*)d_in[7];
    const float* reg_b     = (const float*)d_in[8];
    float* out = (float*)d_out;

    cudaFuncSetAttribute(conv_gemm<1>, cudaFuncAttributeMaxDynamicSharedMemorySize, GSMEM);
    cudaFuncSetAttribute(conv_gemm<2>, cudaFuncAttributeMaxDynamicSharedMemorySize, GSMEM);

    cvt_x16<<<(int)(((size_t)1024*512*56 + 255) / 256), 256>>>(feats);
    cvt_w1h<<<(int)(((size_t)1024*4608 + 255) / 256), 256>>>(w1);
    cvt_wbh<<<(int)(((size_t)1024*9728 + 255) / 256), 256>>>(w2, wd);

    conv_gemm<1><<<dim3(8, 512), 256, GSMEM>>>(out);
    conv_gemm<2><<<dim3(8, 512), 256, GSMEM>>>(out);

    flat_kernel<<<NSAMP, 256>>>(out + O_EMB);
    head_kernel<<<NSAMP, 256>>>(cls_w, cls_b, reg_w, reg_b, out);
    decode_kernel<<<NSAMP, 32>>>(proposals);
    nms_kernel<<<2, 512>>>(out);
}

// round 8
// speedup vs baseline: 1.7221x; 1.7221x over previous
#include <cuda_runtime.h>
#include <cuda_fp16.h>
#include <math.h>
#include <stdint.h>

// ---------------- problem constants ----------------
#define NSAMP   1024
#define NCLS    9
#define PRE_K   512
#define DETS    100
#define IMGW    640.0f
#define IMGH    384.0f

#define O_EMB   ((size_t)0)
#define O_CLS   ((size_t)51380224)
#define O_REG   ((size_t)51389440)
#define O_BOX   ((size_t)51426304)
#define O_SCO   ((size_t)51427104)
#define O_LAB   ((size_t)51427304)
#define O_VAL   ((size_t)51427504)

// packed-M GEMM geometry: 1024 samples x 50 rows (49 valid + 1 pad)
#define MPAD 51200
#define MW   25600           // words per A^T row

// ---------------- scratch (device globals; no allocation) ----------------
#define XN ((size_t)1024*512*56)
#define HN ((size_t)1024*1024*56)
__device__ __align__(16) __half g_x16r [XN + 128];
__device__ __align__(16) __half g_x16lr[XN + 128];
__device__ __align__(16) __half g_x16sr[XN + 128];     // shifted by +1 half
__device__ __align__(16) __half g_x16lsr[XN + 128];
__device__ __align__(16) __half g_h16r [HN + 128];
__device__ __align__(16) __half g_h16lr[HN + 128];
__device__ __align__(16) __half g_h16sr[HN + 128];
__device__ __align__(16) __half g_h16lsr[HN + 128];
#define X16  (g_x16r  + 64)
#define X16L (g_x16lr + 64)
#define X16S (g_x16sr + 64)
#define X16LS (g_x16lsr + 64)
#define H16  (g_h16r  + 64)
#define H16L (g_h16lr + 64)
#define H16S (g_h16sr + 64)
#define H16LS (g_h16lsr + 64)

__device__ __align__(16) __half g_A1h[(size_t)4608*MPAD];   // A^T im2col conv1 hi
__device__ __align__(16) __half g_A1l[(size_t)4608*MPAD];
__device__ __align__(16) __half g_A2h[(size_t)9728*MPAD];   // conv2 (+shortcut cols)
__device__ __align__(16) __half g_A2l[(size_t)9728*MPAD];

__device__ __align__(16) __half g_w1h[(size_t)1024*4608];
__device__ __align__(16) __half g_w1l[(size_t)1024*4608];
__device__ __align__(16) __half g_wbh[(size_t)1024*9728];   // [w2 | wd]
__device__ __align__(16) __half g_wbl[(size_t)1024*9728];

__device__ uint32_t g_mask[9][25];

__device__ float g_flat[(size_t)NSAMP*1024];
__device__ float g_cls[NSAMP*NCLS];
__device__ float g_reg[NSAMP*NCLS*4];
__device__ float g_boxes[NSAMP*NCLS*4];
__device__ float g_scores[NSAMP*NCLS];

// ================= PTX helpers (sm_80-generic) =================
__device__ __forceinline__ uint32_t smem_u32(const void* p) {
    uint32_t a;
    asm("{ .reg .u64 t; cvta.to.shared.u64 t, %1; cvt.u32.u64 %0, t; }" : "=r"(a) : "l"(p));
    return a;
}
__device__ __forceinline__ void cp_async16(uint32_t dst, const void* src) {
    asm volatile("cp.async.cg.shared.global [%0], [%1], 16;" :: "r"(dst), "l"(src) : "memory");
}
#define CP_COMMIT() asm volatile("cp.async.commit_group;" ::: "memory")
#define CP_WAIT2()  asm volatile("cp.async.wait_group 2;" ::: "memory")
#define CP_WAIT0()  asm volatile("cp.async.wait_group 0;" ::: "memory")

__device__ __forceinline__ void ldm_x4(uint32_t* r, uint32_t a) {
    asm volatile("ldmatrix.sync.aligned.m8n8.x4.shared.b16 {%0,%1,%2,%3}, [%4];"
        : "=r"(r[0]), "=r"(r[1]), "=r"(r[2]), "=r"(r[3]) : "r"(a));
}
__device__ __forceinline__ void ldm_x4t(uint32_t* r, uint32_t a) {
    asm volatile("ldmatrix.sync.aligned.m8n8.x4.trans.shared.b16 {%0,%1,%2,%3}, [%4];"
        : "=r"(r[0]), "=r"(r[1]), "=r"(r[2]), "=r"(r[3]) : "r"(a));
}
__device__ __forceinline__ void mma16816(float* c, const uint32_t* a, uint32_t b0, uint32_t b1) {
    asm volatile(
        "mma.sync.aligned.m16n8k16.row.col.f32.f16.f16.f32 "
        "{%0,%1,%2,%3}, {%4,%5,%6,%7}, {%8,%9}, {%0,%1,%2,%3};"
        : "+f"(c[0]), "+f"(c[1]), "+f"(c[2]), "+f"(c[3])
        : "r"(a[0]), "r"(a[1]), "r"(a[2]), "r"(a[3]), "r"(b0), "r"(b1));
}

// ---------------- conversion / prep kernels ----------------
__global__ void cvt_x16(const float* __restrict__ x) {
    size_t i = (size_t)blockIdx.x * 256 + threadIdx.x;
    if (i >= XN) return;
    int p = (int)(i % 56);
    size_t row = i / 56;
    float v = (p < 49) ? x[row * 49 + p] : 0.f;
    __half hh = __float2half(v);
    X16[i]  = hh;
    X16L[i] = __float2half(v - __half2float(hh));
}
__global__ void shift_x() {
    size_t i = (size_t)blockIdx.x * 256 + threadIdx.x;
    if (i >= XN) return;
    X16S[i]  = X16[i + 1];
    X16LS[i] = X16L[i + 1];
}
__global__ void shift_h() {
    size_t i = (size_t)blockIdx.x * 256 + threadIdx.x;
    if (i >= HN) return;
    H16S[i]  = H16[i + 1];
    H16LS[i] = H16L[i + 1];
}
__global__ void cvt_w1h(const float* __restrict__ w) {
    size_t i = (size_t)blockIdx.x * 256 + threadIdx.x;
    if (i >= (size_t)1024*4608) return;
    float v = w[i];
    __half hh = __float2half(v);
    g_w1h[i] = hh;
    g_w1l[i] = __float2half(v - __half2float(hh));
}
__global__ void cvt_wbh(const float* __restrict__ w2, const float* __restrict__ wd) {
    size_t i = (size_t)blockIdx.x * 256 + threadIdx.x;
    if (i >= (size_t)1024*9728) return;
    int co = (int)(i / 9728);
    int kk = (int)(i - (size_t)co * 9728);
    float v = (kk < 9216) ? w2[(size_t)co * 9216 + kk] : wd[(size_t)co * 512 + (kk - 9216)];
    __half hh = __float2half(v);
    g_wbh[i] = hh;
    g_wbl[i] = __float2half(v - __half2float(hh));
}
__global__ void init_mask() {
    int t = threadIdx.x;
    if (t >= 225) return;
    int off = t / 25, w = t - (t / 25) * 25;
    int ky = off / 3, kx = off - (off / 3) * 3;
    uint32_t m = 0;
    #pragma unroll
    for (int h = 0; h < 2; h++) {
        int p = 2 * w + h;
        if (p < 49) {
            int y = p / 7, x = p - (p / 7) * 7;
            int yy = y + ky - 1, xx = x + kx - 1;
            if (yy >= 0 && yy < 7 && xx >= 0 && xx < 7) m |= 0xFFFFu << (16 * h);
        }
    }
    g_mask[off][w] = m;
}

// ---------------- im2col to global A^T (hi + lo) ----------------
// one thread per (kk, n): masked shifted word-copy of one padded image row
template<int P>
__global__ void im2col_kernel() {
    int idx = blockIdx.x * 256 + threadIdx.x;
    int n  = idx & 1023;
    int kk = idx >> 10;
    const int KK = (P == 1) ? 4608 : 9728;
    if (kk >= KK) return;

    int ci, off;
    const __half *H, *Hs, *L, *Ls;
    int CI;
    if (P == 2 && kk >= 9216) {
        ci = kk - 9216; off = 4;                 // center tap, del = 0
        H = X16; Hs = X16S; L = X16L; Ls = X16LS; CI = 512;
    } else {
        ci = kk / 9; off = kk - ci * 9;
        if (P == 1) { H = X16; Hs = X16S; L = X16L; Ls = X16LS; CI = 512; }
        else        { H = H16; Hs = H16S; L = H16L; Ls = H16LS; CI = 1024; }
    }
    int ky = off / 3, kx = off - ky * 3;
    int del = (ky - 1) * 7 + (kx - 1);
    int sh  = del & 1;
    int ws  = (del - sh) >> 1;

    const uint32_t* src  = (const uint32_t*)((sh ? Hs : H) + (size_t)(n * CI + ci) * 56) + ws;
    const uint32_t* srcL = (const uint32_t*)((sh ? Ls : L) + (size_t)(n * CI + ci) * 56) + ws;
    uint32_t* dh = (uint32_t*)((P == 1) ? g_A1h : g_A2h) + (size_t)kk * MW + 25 * n;
    uint32_t* dl = (uint32_t*)((P == 1) ? g_A1l : g_A2l) + (size_t)kk * MW + 25 * n;
    const uint32_t* mk = g_mask[off];
    #pragma unroll
    for (int w = 0; w < 25; w++) {
        uint32_t m = mk[w];
        dh[w] = src[w]  & m;
        dl[w] = srcL[w] & m;
    }
}

// ---------------- pure split-fp16 GEMM (3 products, fp32 acc) ----------------
// smem: Ah/Al [3][64 kk][136 h] (272B rows), Bh/Bl [3][128 co][72 h] (144B rows)
#define AST2 272u
#define BST2 144u
#define A_SZ 17408u
#define B_SZ 18432u
#define AHO(st) ((uint32_t)(st) * A_SZ)
#define ALO(st) (52224u + (uint32_t)(st) * A_SZ)
#define BHO(st) (104448u + (uint32_t)(st) * B_SZ)
#define BLO(st) (159744u + (uint32_t)(st) * B_SZ)
#define GSMEM 215040

__device__ __forceinline__ void mma8(float (*acc)[4], const uint32_t A[2][4],
                                     const uint32_t Q0[4], const uint32_t Q1[4]) {
    #pragma unroll
    for (int i = 0; i < 2; i++) {
        mma16816(acc[i*4+0], A[i], Q0[0], Q0[2]);
        mma16816(acc[i*4+1], A[i], Q0[1], Q0[3]);
        mma16816(acc[i*4+2], A[i], Q1[0], Q1[2]);
        mma16816(acc[i*4+3], A[i], Q1[1], Q1[3]);
    }
}

template<int P>
__global__ void __launch_bounds__(512, 1) gemm_conv(float* __restrict__ d_out) {
    extern __shared__ char smem[];
    const uint32_t sb = smem_u32(smem);
    const int tid  = threadIdx.x;
    const int lane = tid & 31;
    const int wid  = tid >> 5;                 // 16 warps
    const int wm   = wid >> 2, wn = wid & 3;   // 4x4 warp grid, 32x32 tiles
    const int nt   = blockIdx.x;               // 8 n-tiles
    const int mt   = blockIdx.y;               // 400 m-tiles

    const __half* Ah_g = (P == 1) ? g_A1h : g_A2h;
    const __half* Al_g = (P == 1) ? g_A1l : g_A2l;
    const __half* Wh_g = (P == 1) ? g_w1h : g_wbh;
    const __half* Wl_g = (P == 1) ? g_w1l : g_wbl;
    const int KT = (P == 1) ? 4608 : 9728;
    const int NC = KT / 64;

    auto issue = [&](int c) {
        if (c < NC) {
            int st = c - (c / 3) * 3;
            for (int i = tid; i < 1024; i += 512) {
                int r = i >> 4, q = i & 15;
                size_t so = ((size_t)(c * 64 + r) * MPAD + (size_t)mt * 128) * 2 + q * 16;
                uint32_t d = (uint32_t)(r * AST2 + q * 16);
                cp_async16(sb + AHO(st) + d, (const char*)Ah_g + so);
                cp_async16(sb + ALO(st) + d, (const char*)Al_g + so);
            }
            for (int i = tid; i < 1024; i += 512) {
                int r = i >> 3, q = i & 7;
                size_t so = ((size_t)(nt * 128 + r) * KT + c * 64) * 2 + q * 16;
                uint32_t d = (uint32_t)(r * BST2 + q * 16);
                cp_async16(sb + BHO(st) + d, (const char*)Wh_g + so);
                cp_async16(sb + BLO(st) + d, (const char*)Wl_g + so);
            }
        }
        CP_COMMIT();
    };

    float acc[8][4];
    #pragma unroll
    for (int i = 0; i < 8; i++)
        #pragma unroll
        for (int e = 0; e < 4; e++) acc[i][e] = 0.f;

    const uint32_t aRow = ((lane & 7) + ((lane >> 4) & 1) * 8) * AST2
                        + (uint32_t)(wm * 32 + ((lane >> 3) & 1) * 8) * 2u;
    const uint32_t bRow = (uint32_t)(wn * 32 + (lane & 15)) * BST2 + ((lane >> 4) & 1) * 16u;

    issue(0); issue(1); issue(2);

    for (int c = 0; c < NC; c++) {
        int st = c - (c / 3) * 3;
        CP_WAIT2();
        __syncthreads();                       // chunk c resident
        const uint32_t Ahs = sb + AHO(st), Als = sb + ALO(st);
        const uint32_t Bhs = sb + BHO(st), Bls = sb + BLO(st);
        #pragma unroll
        for (int ks = 0; ks < 4; ks++) {
            uint32_t A[2][4], Q0[4], Q1[4], T[2][4];
            ldm_x4t(A[0], Ahs + aRow + (uint32_t)ks * (16u * AST2));
            ldm_x4t(A[1], Ahs + aRow + (uint32_t)ks * (16u * AST2) + 32u);
            ldm_x4(Q0, Bhs + bRow + (uint32_t)ks * 32u);
            ldm_x4(Q1, Bhs + bRow + (uint32_t)ks * 32u + 16u * BST2);
            mma8(&acc[0], A, Q0, Q1);                          // Ah*Bh
            ldm_x4t(T[0], Als + aRow + (uint32_t)ks * (16u * AST2));
            ldm_x4t(T[1], Als + aRow + (uint32_t)ks * (16u * AST2) + 32u);
            mma8(&acc[0], T, Q0, Q1);                          // Al*Bh
            ldm_x4(T[0][0] ? T[0] : T[0], Bls + bRow + (uint32_t)ks * 32u);   // reuse T[0] as B frag
            ldm_x4(T[1], Bls + bRow + (uint32_t)ks * 32u + 16u * BST2);
            mma8(&acc[0], A, T[0], T[1]);                      // Ah*Bl
        }
        __syncthreads();                       // reads done before refill
        issue(c + 3);
    }
    CP_WAIT0();
    __syncthreads();

    // ---- epilogue: stage through smem [128 co][132 m] floats, relu ----
    float* sf = (float*)smem;
    #pragma unroll
    for (int i = 0; i < 2; i++) {
        #pragma unroll
        for (int j = 0; j < 4; j++) {
            int m  = wm * 32 + i * 16 + (lane >> 2);
            int co = wn * 32 + j * 8 + ((lane & 3) << 1);
            const float* a = acc[i*4+j];
            sf[co * 132 + m]           = fmaxf(a[0], 0.f);
            sf[(co + 1) * 132 + m]     = fmaxf(a[1], 0.f);
            sf[co * 132 + m + 8]       = fmaxf(a[2], 0.f);
            sf[(co + 1) * 132 + m + 8] = fmaxf(a[3], 0.f);
        }
    }
    __syncthreads();
    for (int idx = tid; idx < 128 * 128; idx += 512) {
        int co_l = idx >> 7, ml = idx & 127;
        int m_g = mt * 128 + ml;
        int n = m_g / 50;
        int p = m_g - n * 50;
        if (p < 49) {
            float v = sf[co_l * 132 + ml];
            int co_g = nt * 128 + co_l;
            if (P == 1) {
                size_t o = ((size_t)(n * 1024 + co_g)) * 56 + p;
                __half hh = __float2half(v);
                H16[o]  = hh;
                H16L[o] = __float2half(v - __half2float(hh));
            } else {
                d_out[O_EMB + ((size_t)(n * 1024 + co_g)) * 49 + p] = v;
            }
        }
    }
}

// ---------------- avg pool ----------------
__global__ void flat_kernel(const float* __restrict__ emb) {
    int n = blockIdx.x;
    for (int co = threadIdx.x; co < 1024; co += 256) {
        const float* e = emb + ((size_t)n * 1024 + co) * 49;
        float s = 0.f;
        #pragma unroll
        for (int p = 0; p < 49; p++) s += e[p];
        g_flat[(size_t)n * 1024 + co] = s / 49.0f;
    }
}

// ---------------- head GEMMs ----------------
__global__ void head_kernel(const float* __restrict__ cls_w, const float* __restrict__ cls_b,
                            const float* __restrict__ reg_w, const float* __restrict__ reg_b,
                            float* __restrict__ d_out) {
    int n = blockIdx.x;
    int w = threadIdx.x >> 5, lane = threadIdx.x & 31;
    const float* f = g_flat + (size_t)n * 1024;
    for (int o = w; o < 45; o += 8) {
        const float* wr; float bias;
        if (o < NCLS) { wr = cls_w + (size_t)o * 1024; bias = cls_b[o]; }
        else          { wr = reg_w + (size_t)(o - NCLS) * 1024; bias = reg_b[o - NCLS]; }
        float acc = 0.f;
        for (int k = lane; k < 1024; k += 32) acc += f[k] * wr[k];
        #pragma unroll
        for (int d = 16; d; d >>= 1) acc += __shfl_xor_sync(0xffffffffu, acc, d);
        if (lane == 0) {
            float v = acc + bias;
            if (o < NCLS) { g_cls[n * NCLS + o] = v; d_out[O_CLS + n * NCLS + o] = v; }
            else { g_reg[n * 36 + (o - NCLS)] = v; d_out[O_REG + n * 36 + (o - NCLS)] = v; }
        }
    }
}

// ---------------- softmax + box decode + clip ----------------
__global__ void decode_kernel(const float* __restrict__ proposals) {
    int n = blockIdx.x; int lane = threadIdx.x;
    float logit = (lane < NCLS) ? g_cls[n * NCLS + lane] : -INFINITY;
    float m = logit;
    #pragma unroll
    for (int d = 16; d; d >>= 1) m = fmaxf(m, __shfl_xor_sync(0xffffffffu, m, d));
    float e = (lane < NCLS) ? expf(logit - m) : 0.f;
    float s = e;
    #pragma unroll
    for (int d = 16; d; d >>= 1) s += __shfl_xor_sync(0xffffffffu, s, d);
    if (lane < NCLS) {
        g_scores[n * NCLS + lane] = e / s;
        const float* pr = proposals + (size_t)n * 4;
        float pw = pr[2] - pr[0], ph = pr[3] - pr[1];
        float pcx = pr[0] + 0.5f * pw, pcy = pr[1] + 0.5f * ph;
        const float* rr = g_reg + n * 36 + lane * 4;
        float dx = rr[0] / 10.0f, dy = rr[1] / 10.0f;
        float dw = fminf(rr[2] / 5.0f, 4.135166556742356f);
        float dh = fminf(rr[3] / 5.0f, 4.135166556742356f);
        float ncx = dx * pw + pcx, ncy = dy * ph + pcy;
        float nw = expf(dw) * pw, nh = expf(dh) * ph;
        float b0 = fminf(fmaxf(ncx - 0.5f * nw, 0.f), IMGW);
        float b1 = fminf(fmaxf(ncy - 0.5f * nh, 0.f), IMGH);
        float b2 = fminf(fmaxf(ncx + 0.5f * nw, 0.f), IMGW);
        float b3 = fminf(fmaxf(ncy + 0.5f * nh, 0.f), IMGH);
        float* bp = g_boxes + (size_t)(n * NCLS + lane) * 4;
        bp[0] = b0; bp[1] = b1; bp[2] = b2; bp[3] = b3;
    }
}

// ---------------- per-image: filter -> sort(4096) -> NMS(512) -> top-100 ----------------
__global__ void __launch_bounds__(512) nms_kernel(float* __restrict__ d_out) {
    __shared__ float skey[4096];
    __shared__ int   sidx[4096];
    __shared__ float sbox[PRE_K * 4];
    __shared__ int   skeep[PRE_K];
    __shared__ int   swsum[16];

    int img = blockIdx.x; int tid = threadIdx.x;

    for (int j = tid; j < 4096; j += 512) {
        int p = j >> 3, c = (j & 7) + 1;
        int n = img * 512 + p;
        float s = g_scores[n * NCLS + c];
        const float* bb = g_boxes + (size_t)(n * NCLS + c) * 4;
        bool valid = (s > 0.05f) && ((bb[2] - bb[0]) >= 0.01f) && ((bb[3] - bb[1]) >= 0.01f);
        skey[j] = valid ? s : -INFINITY;
        sidx[j] = j;
    }
    __syncthreads();

    for (int k = 2; k <= 4096; k <<= 1) {
        for (int j2 = k >> 1; j2 > 0; j2 >>= 1) {
            for (int i = tid; i < 4096; i += 512) {
                int ixj = i ^ j2;
                if (ixj > i) {
                    float ka = skey[i], kb = skey[ixj];
                    int ia = sidx[i], ib = sidx[ixj];
                    bool a_first = (ka > kb) || (ka == kb && ia < ib);
                    bool up = ((i & k) == 0);
                    if (up ? !a_first : a_first) {
                        skey[i] = kb; skey[ixj] = ka;
                        sidx[i] = ib; sidx[ixj] = ia;
                    }
                }
            }
            __syncthreads();
        }
    }

    if (tid < PRE_K) {
        float s = skey[tid];
        int j = sidx[tid];
        int p = j >> 3, c = (j & 7) + 1;
        int n = img * 512 + p;
        const float* bb = g_boxes + (size_t)(n * NCLS + c) * 4;
        float off = 641.0f * (float)c;
        sbox[tid * 4 + 0] = bb[0] + off;
        sbox[tid * 4 + 1] = bb[1] + off;
        sbox[tid * 4 + 2] = bb[2] + off;
        sbox[tid * 4 + 3] = bb[3] + off;
        skeep[tid] = (s != -INFINITY) ? 1 : 0;
    }
    __syncthreads();

    for (int i = 0; i < PRE_K; i++) {
        if (skeep[i]) {
            int j = tid;
            if (j > i && skeep[j]) {
                float ax0 = sbox[i*4], ay0 = sbox[i*4+1], ax1 = sbox[i*4+2], ay1 = sbox[i*4+3];
                float bx0 = sbox[j*4], by0 = sbox[j*4+1], bx1 = sbox[j*4+2], by1 = sbox[j*4+3];
                float areaA = (ax1 - ax0) * (ay1 - ay0);
                float areaB = (bx1 - bx0) * (by1 - by0);
                float iw = fmaxf(fminf(ax1, bx1) - fmaxf(ax0, bx0), 0.f);
                float ih = fmaxf(fminf(ay1, by1) - fmaxf(ay0, by0), 0.f);
                float inter = iw * ih;
                float iou = inter / fmaxf(areaA + areaB - inter, 1e-8f);
                if (iou > 0.5f) skeep[j] = 0;
            }
        }
        __syncthreads();
    }

    int keepflag = (tid < PRE_K) ? skeep[tid] : 0;
    unsigned mask = __ballot_sync(0xffffffffu, keepflag != 0);
    int lane = tid & 31, wid = tid >> 5;
    if (lane == 0) swsum[wid] = __popc(mask);
    __syncthreads();
    int base = 0;
    for (int w = 0; w < wid; w++) base += swsum[w];
    int rank = base + __popc(mask & ((1u << lane) - 1u));

    float* dbx = d_out + O_BOX + (size_t)img * DETS * 4;
    float* dsc = d_out + O_SCO + (size_t)img * DETS;
    float* dlb = d_out + O_LAB + (size_t)img * DETS;
    float* dvl = d_out + O_VAL + (size_t)img * DETS;
    for (int i = tid; i < DETS; i += 512) {
        dbx[i*4+0] = 0.f; dbx[i*4+1] = 0.f; dbx[i*4+2] = 0.f; dbx[i*4+3] = 0.f;
        dsc[i] = 0.f; dlb[i] = 0.f; dvl[i] = 0.f;
    }
    __syncthreads();
    if (keepflag && rank < DETS) {
        int j = sidx[tid];
        int p = j >> 3, c = (j & 7) + 1;
        int n = img * 512 + p;
        const float* bb = g_boxes + (size_t)(n * NCLS + c) * 4;
        dbx[rank*4+0] = bb[0]; dbx[rank*4+1] = bb[1];
        dbx[rank*4+2] = bb[2]; dbx[rank*4+3] = bb[3];
        dsc[rank] = skey[tid];
        dlb[rank] = (float)c;
        dvl[rank] = 1.0f;
    }
}

// ---------------- launch ----------------
extern "C" void kernel_launch(void* const* d_in, const int* in_sizes, int n_in,
                              void* d_out, int out_size) {
    const float* feats     = (const float*)d_in[0];
    const float* proposals = (const float*)d_in[1];
    const float* w1        = (const float*)d_in[2];
    const float* w2        = (const float*)d_in[3];
    const float* wd        = (const float*)d_in[4];
    const float* cls_w     = (const float*)d_in[5];
    const float* cls_b     = (const float*)d_in[6];
    const float* reg_w     = (const float*)d_in[7];
    const float* reg_b     = (const float*)d_in[8];
    float* out = (float*)d_out;

    cudaFuncSetAttribute(gemm_conv<1>, cudaFuncAttributeMaxDynamicSharedMemorySize, GSMEM);
    cudaFuncSetAttribute(gemm_conv<2>, cudaFuncAttributeMaxDynamicSharedMemorySize, GSMEM);

    cvt_x16<<<(int)((XN + 255) / 256), 256>>>(feats);
    shift_x<<<(int)((XN + 255) / 256), 256>>>();
    cvt_w1h<<<(int)(((size_t)1024*4608 + 255) / 256), 256>>>(w1);
    cvt_wbh<<<(int)(((size_t)1024*9728 + 255) / 256), 256>>>(w2, wd);
    init_mask<<<1, 256>>>();

    im2col_kernel<1><<<4608 * 4, 256>>>();               // 4608*1024/256
    gemm_conv<1><<<dim3(8, 400), 512, GSMEM>>>(out);

    shift_h<<<(int)((HN + 255) / 256), 256>>>();
    im2col_kernel<2><<<9728 * 4, 256>>>();
    gemm_conv<2><<<dim3(8, 400), 512, GSMEM>>>(out);

    flat_kernel<<<NSAMP, 256>>>(out + O_EMB);
    head_kernel<<<NSAMP, 256>>>(cls_w, cls_b, reg_w, reg_b, out);
    decode_kernel<<<NSAMP, 32>>>(proposals);
    nms_kernel<<<2, 512>>>(out);
}

// round 9
// speedup vs baseline: 1.7423x; 1.0117x over previous
#include <cuda_runtime.h>
#include <cuda_fp16.h>
#include <math.h>
#include <stdint.h>

// ---------------- problem constants ----------------
#define NSAMP   1024
#define NCLS    9
#define PRE_K   512
#define DETS    100
#define IMGW    640.0f
#define IMGH    384.0f

#define O_EMB   ((size_t)0)
#define O_CLS   ((size_t)51380224)
#define O_REG   ((size_t)51389440)
#define O_BOX   ((size_t)51426304)
#define O_SCO   ((size_t)51427104)
#define O_LAB   ((size_t)51427304)
#define O_VAL   ((size_t)51427504)

// packed-M GEMM geometry: 1024 samples x 50 rows (49 valid + 1 pad)
#define MPAD 51200
#define MW   25600           // words per A^T row

// ---------------- scratch (device globals; no allocation) ----------------
#define XN ((size_t)1024*512*56)
#define HN ((size_t)1024*1024*56)
__device__ __align__(16) __half g_x16r [XN + 128];
__device__ __align__(16) __half g_x16lr[XN + 128];
__device__ __align__(16) __half g_x16sr[XN + 128];     // shifted by +1 half
__device__ __align__(16) __half g_x16lsr[XN + 128];
__device__ __align__(16) __half g_h16r [HN + 128];
__device__ __align__(16) __half g_h16lr[HN + 128];
__device__ __align__(16) __half g_h16sr[HN + 128];
__device__ __align__(16) __half g_h16lsr[HN + 128];
#define X16  (g_x16r  + 64)
#define X16L (g_x16lr + 64)
#define X16S (g_x16sr + 64)
#define X16LS (g_x16lsr + 64)
#define H16  (g_h16r  + 64)
#define H16L (g_h16lr + 64)
#define H16S (g_h16sr + 64)
#define H16LS (g_h16lsr + 64)

__device__ __align__(16) __half g_A1h[(size_t)4608*MPAD];   // A^T im2col conv1 hi
__device__ __align__(16) __half g_A1l[(size_t)4608*MPAD];
__device__ __align__(16) __half g_A2h[(size_t)9728*MPAD];   // conv2 (+shortcut cols)
__device__ __align__(16) __half g_A2l[(size_t)9728*MPAD];

__device__ __align__(16) __half g_w1h[(size_t)1024*4608];
__device__ __align__(16) __half g_w1l[(size_t)1024*4608];
__device__ __align__(16) __half g_wbh[(size_t)1024*9728];   // [w2 | wd]
__device__ __align__(16) __half g_wbl[(size_t)1024*9728];

__device__ uint32_t g_mask[9][25];

__device__ float g_flat[(size_t)NSAMP*1024];
__device__ float g_cls[NSAMP*NCLS];
__device__ float g_reg[NSAMP*NCLS*4];
__device__ float g_boxes[NSAMP*NCLS*4];
__device__ float g_scores[NSAMP*NCLS];

// ================= PTX helpers (sm_80-generic) =================
__device__ __forceinline__ uint32_t smem_u32(const void* p) {
    uint32_t a;
    asm("{ .reg .u64 t; cvta.to.shared.u64 t, %1; cvt.u32.u64 %0, t; }" : "=r"(a) : "l"(p));
    return a;
}
__device__ __forceinline__ void cp_async16(uint32_t dst, const void* src) {
    asm volatile("cp.async.cg.shared.global [%0], [%1], 16;" :: "r"(dst), "l"(src) : "memory");
}
#define CP_COMMIT() asm volatile("cp.async.commit_group;" ::: "memory")
#define CP_WAIT1()  asm volatile("cp.async.wait_group 1;" ::: "memory")
#define CP_WAIT0()  asm volatile("cp.async.wait_group 0;" ::: "memory")

__device__ __forceinline__ void ldm_x4(uint32_t* r, uint32_t a) {
    asm volatile("ldmatrix.sync.aligned.m8n8.x4.shared.b16 {%0,%1,%2,%3}, [%4];"
        : "=r"(r[0]), "=r"(r[1]), "=r"(r[2]), "=r"(r[3]) : "r"(a));
}
__device__ __forceinline__ void ldm_x4t(uint32_t* r, uint32_t a) {
    asm volatile("ldmatrix.sync.aligned.m8n8.x4.trans.shared.b16 {%0,%1,%2,%3}, [%4];"
        : "=r"(r[0]), "=r"(r[1]), "=r"(r[2]), "=r"(r[3]) : "r"(a));
}
__device__ __forceinline__ void mma16816(float* c, const uint32_t* a, uint32_t b0, uint32_t b1) {
    asm volatile(
        "mma.sync.aligned.m16n8k16.row.col.f32.f16.f16.f32 "
        "{%0,%1,%2,%3}, {%4,%5,%6,%7}, {%8,%9}, {%0,%1,%2,%3};"
        : "+f"(c[0]), "+f"(c[1]), "+f"(c[2]), "+f"(c[3])
        : "r"(a[0]), "r"(a[1]), "r"(a[2]), "r"(a[3]), "r"(b0), "r"(b1));
}

// ---------------- conversion / prep kernels ----------------
__global__ void cvt_x16(const float* __restrict__ x) {
    size_t i = (size_t)blockIdx.x * 256 + threadIdx.x;
    if (i >= XN) return;
    int p = (int)(i % 56);
    size_t row = i / 56;
    float v = (p < 49) ? x[row * 49 + p] : 0.f;
    __half hh = __float2half(v);
    X16[i]  = hh;
    X16L[i] = __float2half(v - __half2float(hh));
}
__global__ void shift_x() {
    size_t i = (size_t)blockIdx.x * 256 + threadIdx.x;
    if (i >= XN) return;
    X16S[i]  = X16[i + 1];
    X16LS[i] = X16L[i + 1];
}
__global__ void shift_h() {
    size_t i = (size_t)blockIdx.x * 256 + threadIdx.x;
    if (i >= HN) return;
    H16S[i]  = H16[i + 1];
    H16LS[i] = H16L[i + 1];
}
__global__ void cvt_w1h(const float* __restrict__ w) {
    size_t i = (size_t)blockIdx.x * 256 + threadIdx.x;
    if (i >= (size_t)1024*4608) return;
    float v = w[i];
    __half hh = __float2half(v);
    g_w1h[i] = hh;
    g_w1l[i] = __float2half(v - __half2float(hh));
}
__global__ void cvt_wbh(const float* __restrict__ w2, const float* __restrict__ wd) {
    size_t i = (size_t)blockIdx.x * 256 + threadIdx.x;
    if (i >= (size_t)1024*9728) return;
    int co = (int)(i / 9728);
    int kk = (int)(i - (size_t)co * 9728);
    float v = (kk < 9216) ? w2[(size_t)co * 9216 + kk] : wd[(size_t)co * 512 + (kk - 9216)];
    __half hh = __float2half(v);
    g_wbh[i] = hh;
    g_wbl[i] = __float2half(v - __half2float(hh));
}
__global__ void init_mask() {
    int t = threadIdx.x;
    if (t >= 225) return;
    int off = t / 25, w = t - (t / 25) * 25;
    int ky = off / 3, kx = off - (off / 3) * 3;
    uint32_t m = 0;
    #pragma unroll
    for (int h = 0; h < 2; h++) {
        int p = 2 * w + h;
        if (p < 49) {
            int y = p / 7, x = p - (p / 7) * 7;
            int yy = y + ky - 1, xx = x + kx - 1;
            if (yy >= 0 && yy < 7 && xx >= 0 && xx < 7) m |= 0xFFFFu << (16 * h);
        }
    }
    g_mask[off][w] = m;
}

// ---------------- im2col to global A^T (hi + lo) ----------------
template<int P>
__global__ void im2col_kernel() {
    int idx = blockIdx.x * 256 + threadIdx.x;
    int n  = idx & 1023;
    int kk = idx >> 10;
    const int KK = (P == 1) ? 4608 : 9728;
    if (kk >= KK) return;

    int ci, off;
    const __half *H, *Hs, *L, *Ls;
    int CI;
    if (P == 2 && kk >= 9216) {
        ci = kk - 9216; off = 4;                 // center tap, del = 0
        H = X16; Hs = X16S; L = X16L; Ls = X16LS; CI = 512;
    } else {
        ci = kk / 9; off = kk - ci * 9;
        if (P == 1) { H = X16; Hs = X16S; L = X16L; Ls = X16LS; CI = 512; }
        else        { H = H16; Hs = H16S; L = H16L; Ls = H16LS; CI = 1024; }
    }
    int ky = off / 3, kx = off - ky * 3;
    int del = (ky - 1) * 7 + (kx - 1);
    int sh  = del & 1;
    int ws  = (del - sh) >> 1;

    const uint32_t* src  = (const uint32_t*)((sh ? Hs : H) + (size_t)(n * CI + ci) * 56) + ws;
    const uint32_t* srcL = (const uint32_t*)((sh ? Ls : L) + (size_t)(n * CI + ci) * 56) + ws;
    uint32_t* dh = (uint32_t*)((P == 1) ? g_A1h : g_A2h) + (size_t)kk * MW + 25 * n;
    uint32_t* dl = (uint32_t*)((P == 1) ? g_A1l : g_A2l) + (size_t)kk * MW + 25 * n;
    const uint32_t* mk = g_mask[off];
    #pragma unroll
    for (int w = 0; w < 25; w++) {
        uint32_t m = mk[w];
        dh[w] = src[w]  & m;
        dl[w] = srcL[w] & m;
    }
}

// ---------------- pure split-fp16 GEMM (3 products, fp32 acc) ----------------
// smem: Ah/Al [3][64 kk][136 h] (272B rows), Bh/Bl [3][128 co][72 h] (144B rows)
#define AST2 272u
#define BST2 144u
#define A_SZ 17408u
#define B_SZ 18432u
#define AHO(st) ((uint32_t)(st) * A_SZ)
#define ALO(st) (52224u + (uint32_t)(st) * A_SZ)
#define BHO(st) (104448u + (uint32_t)(st) * B_SZ)
#define BLO(st) (159744u + (uint32_t)(st) * B_SZ)
#define GSMEM 215040

__device__ __forceinline__ void mma8(float (*acc)[4], const uint32_t A[2][4],
                                     const uint32_t Q0[4], const uint32_t Q1[4]) {
    #pragma unroll
    for (int i = 0; i < 2; i++) {
        mma16816(acc[i*4+0], A[i], Q0[0], Q0[2]);
        mma16816(acc[i*4+1], A[i], Q0[1], Q0[3]);
        mma16816(acc[i*4+2], A[i], Q1[0], Q1[2]);
        mma16816(acc[i*4+3], A[i], Q1[1], Q1[3]);
    }
}

template<int P>
__global__ void __launch_bounds__(512, 1) gemm_conv(float* __restrict__ d_out) {
    extern __shared__ char smem[];
    const uint32_t sb = smem_u32(smem);
    const int tid  = threadIdx.x;
    const int lane = tid & 31;
    const int wid  = tid >> 5;                 // 16 warps
    const int wm   = wid >> 2, wn = wid & 3;   // 4x4 warp grid, 32x32 tiles
    const int nt   = blockIdx.x;               // 8 n-tiles
    const int mt   = blockIdx.y;               // 400 m-tiles

    const __half* Ah_g = (P == 1) ? g_A1h : g_A2h;
    const __half* Al_g = (P == 1) ? g_A1l : g_A2l;
    const __half* Wh_g = (P == 1) ? g_w1h : g_wbh;
    const __half* Wl_g = (P == 1) ? g_w1l : g_wbl;
    const int KT = (P == 1) ? 4608 : 9728;
    const int NC = KT / 64;

    auto issue = [&](int c) {
        if (c < NC) {
            int st = c - (c / 3) * 3;
            for (int i = tid; i < 1024; i += 512) {
                int r = i >> 4, q = i & 15;
                size_t so = ((size_t)(c * 64 + r) * MPAD + (size_t)mt * 128) * 2 + q * 16;
                uint32_t d = (uint32_t)(r * AST2 + q * 16);
                cp_async16(sb + AHO(st) + d, (const char*)Ah_g + so);
                cp_async16(sb + ALO(st) + d, (const char*)Al_g + so);
            }
            for (int i = tid; i < 1024; i += 512) {
                int r = i >> 3, q = i & 7;
                size_t so = ((size_t)(nt * 128 + r) * KT + c * 64) * 2 + q * 16;
                uint32_t d = (uint32_t)(r * BST2 + q * 16);
                cp_async16(sb + BHO(st) + d, (const char*)Wh_g + so);
                cp_async16(sb + BLO(st) + d, (const char*)Wl_g + so);
            }
        }
        CP_COMMIT();
    };

    float acc[8][4];
    #pragma unroll
    for (int i = 0; i < 8; i++)
        #pragma unroll
        for (int e = 0; e < 4; e++) acc[i][e] = 0.f;

    const uint32_t aRow = ((lane & 7) + ((lane >> 4) & 1) * 8) * AST2
                        + (uint32_t)(wm * 32 + ((lane >> 3) & 1) * 8) * 2u;
    const uint32_t bRow = (uint32_t)(wn * 32 + (lane & 15)) * BST2 + ((lane >> 4) & 1) * 16u;

    // prefetch distance 2, 3 stages -> refill target was drained 1 chunk ago
    issue(0); issue(1);

    for (int c = 0; c < NC; c++) {
        int st = c - (c / 3) * 3;
        CP_WAIT1();                            // group c complete (c+1 may be pending)
        __syncthreads();                       // everyone done with stage (c-1)%3 too
        issue(c + 2);                          // writes stage (c+2)%3 == (c-1)%3
        const uint32_t Ahs = sb + AHO(st), Als = sb + ALO(st);
        const uint32_t Bhs = sb + BHO(st), Bls = sb + BLO(st);
        #pragma unroll
        for (int ks = 0; ks < 4; ks++) {
            uint32_t A[2][4], AL[2][4], Q0[4], Q1[4], R0[4], R1[4];
            const uint32_t ao = aRow + (uint32_t)ks * (16u * AST2);
            const uint32_t bo = bRow + (uint32_t)ks * 32u;
            ldm_x4t(A[0],  Ahs + ao);
            ldm_x4t(A[1],  Ahs + ao + 32u);
            ldm_x4t(AL[0], Als + ao);
            ldm_x4t(AL[1], Als + ao + 32u);
            ldm_x4(Q0, Bhs + bo);
            ldm_x4(Q1, Bhs + bo + 16u * BST2);
            ldm_x4(R0, Bls + bo);
            ldm_x4(R1, Bls + bo + 16u * BST2);
            mma8(&acc[0], A,  Q0, Q1);         // Ah*Bh
            mma8(&acc[0], AL, Q0, Q1);         // Al*Bh
            mma8(&acc[0], A,  R0, R1);         // Ah*Bl
        }
    }
    CP_WAIT0();
    __syncthreads();

    // ---- epilogue: stage through smem [128 co][132 m] floats, relu ----
    float* sf = (float*)smem;
    #pragma unroll
    for (int i = 0; i < 2; i++) {
        #pragma unroll
        for (int j = 0; j < 4; j++) {
            int m  = wm * 32 + i * 16 + (lane >> 2);
            int co = wn * 32 + j * 8 + ((lane & 3) << 1);
            const float* a = acc[i*4+j];
            sf[co * 132 + m]           = fmaxf(a[0], 0.f);
            sf[(co + 1) * 132 + m]     = fmaxf(a[1], 0.f);
            sf[co * 132 + m + 8]       = fmaxf(a[2], 0.f);
            sf[(co + 1) * 132 + m + 8] = fmaxf(a[3], 0.f);
        }
    }
    __syncthreads();
    for (int idx = tid; idx < 128 * 128; idx += 512) {
        int co_l = idx >> 7, ml = idx & 127;
        int m_g = mt * 128 + ml;
        int n = m_g / 50;
        int p = m_g - n * 50;
        if (p < 49) {
            float v = sf[co_l * 132 + ml];
            int co_g = nt * 128 + co_l;
            if (P == 1) {
                size_t o = ((size_t)(n * 1024 + co_g)) * 56 + p;
                __half hh = __float2half(v);
                H16[o]  = hh;
                H16L[o] = __float2half(v - __half2float(hh));
            } else {
                d_out[O_EMB + ((size_t)(n * 1024 + co_g)) * 49 + p] = v;
            }
        }
    }
}

// ---------------- avg pool ----------------
__global__ void flat_kernel(const float* __restrict__ emb) {
    int n = blockIdx.x;
    for (int co = threadIdx.x; co < 1024; co += 256) {
        const float* e = emb + ((size_t)n * 1024 + co) * 49;
        float s = 0.f;
        #pragma unroll
        for (int p = 0; p < 49; p++) s += e[p];
        g_flat[(size_t)n * 1024 + co] = s / 49.0f;
    }
}

// ---------------- head GEMMs ----------------
__global__ void head_kernel(const float* __restrict__ cls_w, const float* __restrict__ cls_b,
                            const float* __restrict__ reg_w, const float* __restrict__ reg_b,
                            float* __restrict__ d_out) {
    int n = blockIdx.x;
    int w = threadIdx.x >> 5, lane = threadIdx.x & 31;
    const float* f = g_flat + (size_t)n * 1024;
    for (int o = w; o < 45; o += 8) {
        const float* wr; float bias;
        if (o < NCLS) { wr = cls_w + (size_t)o * 1024; bias = cls_b[o]; }
        else          { wr = reg_w + (size_t)(o - NCLS) * 1024; bias = reg_b[o - NCLS]; }
        float acc = 0.f;
        for (int k = lane; k < 1024; k += 32) acc += f[k] * wr[k];
        #pragma unroll
        for (int d = 16; d; d >>= 1) acc += __shfl_xor_sync(0xffffffffu, acc, d);
        if (lane == 0) {
            float v = acc + bias;
            if (o < NCLS) { g_cls[n * NCLS + o] = v; d_out[O_CLS + n * NCLS + o] = v; }
            else { g_reg[n * 36 + (o - NCLS)] = v; d_out[O_REG + n * 36 + (o - NCLS)] = v; }
        }
    }
}

// ---------------- softmax + box decode + clip ----------------
__global__ void decode_kernel(const float* __restrict__ proposals) {
    int n = blockIdx.x; int lane = threadIdx.x;
    float logit = (lane < NCLS) ? g_cls[n * NCLS + lane] : -INFINITY;
    float m = logit;
    #pragma unroll
    for (int d = 16; d; d >>= 1) m = fmaxf(m, __shfl_xor_sync(0xffffffffu, m, d));
    float e = (lane < NCLS) ? expf(logit - m) : 0.f;
    float s = e;
    #pragma unroll
    for (int d = 16; d; d >>= 1) s += __shfl_xor_sync(0xffffffffu, s, d);
    if (lane < NCLS) {
        g_scores[n * NCLS + lane] = e / s;
        const float* pr = proposals + (size_t)n * 4;
        float pw = pr[2] - pr[0], ph = pr[3] - pr[1];
        float pcx = pr[0] + 0.5f * pw, pcy = pr[1] + 0.5f * ph;
        const float* rr = g_reg + n * 36 + lane * 4;
        float dx = rr[0] / 10.0f, dy = rr[1] / 10.0f;
        float dw = fminf(rr[2] / 5.0f, 4.135166556742356f);
        float dh = fminf(rr[3] / 5.0f, 4.135166556742356f);
        float ncx = dx * pw + pcx, ncy = dy * ph + pcy;
        float nw = expf(dw) * pw, nh = expf(dh) * ph;
        float b0 = fminf(fmaxf(ncx - 0.5f * nw, 0.f), IMGW);
        float b1 = fminf(fmaxf(ncy - 0.5f * nh, 0.f), IMGH);
        float b2 = fminf(fmaxf(ncx + 0.5f * nw, 0.f), IMGW);
        float b3 = fminf(fmaxf(ncy + 0.5f * nh, 0.f), IMGH);
        float* bp = g_boxes + (size_t)(n * NCLS + lane) * 4;
        bp[0] = b0; bp[1] = b1; bp[2] = b2; bp[3] = b3;
    }
}

// ---------------- per-image: filter -> sort(4096) -> NMS(512) -> top-100 ----------------
__global__ void __launch_bounds__(512) nms_kernel(float* __restrict__ d_out) {
    __shared__ float skey[4096];
    __shared__ int   sidx[4096];
    __shared__ float sbox[PRE_K * 4];
    __shared__ int   skeep[PRE_K];
    __shared__ int   swsum[16];

    int img = blockIdx.x; int tid = threadIdx.x;

    for (int j = tid; j < 4096; j += 512) {
        int p = j >> 3, c = (j & 7) + 1;
        int n = img * 512 + p;
        float s = g_scores[n * NCLS + c];
        const float* bb = g_boxes + (size_t)(n * NCLS + c) * 4;
        bool valid = (s > 0.05f) && ((bb[2] - bb[0]) >= 0.01f) && ((bb[3] - bb[1]) >= 0.01f);
        skey[j] = valid ? s : -INFINITY;
        sidx[j] = j;
    }
    __syncthreads();

    for (int k = 2; k <= 4096; k <<= 1) {
        for (int j2 = k >> 1; j2 > 0; j2 >>= 1) {
            for (int i = tid; i < 4096; i += 512) {
                int ixj = i ^ j2;
                if (ixj > i) {
                    float ka = skey[i], kb = skey[ixj];
                    int ia = sidx[i], ib = sidx[ixj];
                    bool a_first = (ka > kb) || (ka == kb && ia < ib);
                    bool up = ((i & k) == 0);
                    if (up ? !a_first : a_first) {
                        skey[i] = kb; skey[ixj] = ka;
                        sidx[i] = ib; sidx[ixj] = ia;
                    }
                }
            }
            __syncthreads();
        }
    }

    if (tid < PRE_K) {
        float s = skey[tid];
        int j = sidx[tid];
        int p = j >> 3, c = (j & 7) + 1;
        int n = img * 512 + p;
        const float* bb = g_boxes + (size_t)(n * NCLS + c) * 4;
        float off = 641.0f * (float)c;
        sbox[tid * 4 + 0] = bb[0] + off;
        sbox[tid * 4 + 1] = bb[1] + off;
        sbox[tid * 4 + 2] = bb[2] + off;
        sbox[tid * 4 + 3] = bb[3] + off;
        skeep[tid] = (s != -INFINITY) ? 1 : 0;
    }
    __syncthreads();

    for (int i = 0; i < PRE_K; i++) {
        if (skeep[i]) {
            int j = tid;
            if (j > i && skeep[j]) {
                float ax0 = sbox[i*4], ay0 = sbox[i*4+1], ax1 = sbox[i*4+2], ay1 = sbox[i*4+3];
                float bx0 = sbox[j*4], by0 = sbox[j*4+1], bx1 = sbox[j*4+2], by1 = sbox[j*4+3];
                float areaA = (ax1 - ax0) * (ay1 - ay0);
                float areaB = (bx1 - bx0) * (by1 - by0);
                float iw = fmaxf(fminf(ax1, bx1) - fmaxf(ax0, bx0), 0.f);
                float ih = fmaxf(fminf(ay1, by1) - fmaxf(ay0, by0), 0.f);
                float inter = iw * ih;
                float iou = inter / fmaxf(areaA + areaB - inter, 1e-8f);
                if (iou > 0.5f) skeep[j] = 0;
            }
        }
        __syncthreads();
    }

    int keepflag = (tid < PRE_K) ? skeep[tid] : 0;
    unsigned mask = __ballot_sync(0xffffffffu, keepflag != 0);
    int lane = tid & 31, wid = tid >> 5;
    if (lane == 0) swsum[wid] = __popc(mask);
    __syncthreads();
    int base = 0;
    for (int w = 0; w < wid; w++) base += swsum[w];
    int rank = base + __popc(mask & ((1u << lane) - 1u));

    float* dbx = d_out + O_BOX + (size_t)img * DETS * 4;
    float* dsc = d_out + O_SCO + (size_t)img * DETS;
    float* dlb = d_out + O_LAB + (size_t)img * DETS;
    float* dvl = d_out + O_VAL + (size_t)img * DETS;
    for (int i = tid; i < DETS; i += 512) {
        dbx[i*4+0] = 0.f; dbx[i*4+1] = 0.f; dbx[i*4+2] = 0.f; dbx[i*4+3] = 0.f;
        dsc[i] = 0.f; dlb[i] = 0.f; dvl[i] = 0.f;
    }
    __syncthreads();
    if (keepflag && rank < DETS) {
        int j = sidx[tid];
        int p = j >> 3, c = (j & 7) + 1;
        int n = img * 512 + p;
        const float* bb = g_boxes + (size_t)(n * NCLS + c) * 4;
        dbx[rank*4+0] = bb[0]; dbx[rank*4+1] = bb[1];
        dbx[rank*4+2] = bb[2]; dbx[rank*4+3] = bb[3];
        dsc[rank] = skey[tid];
        dlb[rank] = (float)c;
        dvl[rank] = 1.0f;
    }
}

// ---------------- launch ----------------
extern "C" void kernel_launch(void* const* d_in, const int* in_sizes, int n_in,
                              void* d_out, int out_size) {
    const float* feats     = (const float*)d_in[0];
    const float* proposals = (const float*)d_in[1];
    const float* w1        = (const float*)d_in[2];
    const float* w2        = (const float*)d_in[3];
    const float* wd        = (const float*)d_in[4];
    const float* cls_w     = (const float*)d_in[5];
    const float* cls_b     = (const float*)d_in[6];
    const float* reg_w     = (const float*)d_in[7];
    const float* reg_b     = (const float*)d_in[8];
    float* out = (float*)d_out;

    cudaFuncSetAttribute(gemm_conv<1>, cudaFuncAttributeMaxDynamicSharedMemorySize, GSMEM);
    cudaFuncSetAttribute(gemm_conv<2>, cudaFuncAttributeMaxDynamicSharedMemorySize, GSMEM);

    cvt_x16<<<(int)((XN + 255) / 256), 256>>>(feats);
    shift_x<<<(int)((XN + 255) / 256), 256>>>();
    cvt_w1h<<<(int)(((size_t)1024*4608 + 255) / 256), 256>>>(w1);
    cvt_wbh<<<(int)(((size_t)1024*9728 + 255) / 256), 256>>>(w2, wd);
    init_mask<<<1, 256>>>();

    im2col_kernel<1><<<4608 * 4, 256>>>();
    gemm_conv<1><<<dim3(8, 400), 512, GSMEM>>>(out);

    shift_h<<<(int)((HN + 255) / 256), 256>>>();
    im2col_kernel<2><<<9728 * 4, 256>>>();
    gemm_conv<2><<<dim3(8, 400), 512, GSMEM>>>(out);

    flat_kernel<<<NSAMP, 256>>>(out + O_EMB);
    head_kernel<<<NSAMP, 256>>>(cls_w, cls_b, reg_w, reg_b, out);
    decode_kernel<<<NSAMP, 32>>>(proposals);
    nms_kernel<<<2, 512>>>(out);
}

// round 10
// speedup vs baseline: 1.9863x; 1.1401x over previous
#include <cuda_runtime.h>
#include <cuda_fp16.h>
#include <math.h>
#include <stdint.h>

// ---------------- problem constants ----------------
#define NSAMP   1024
#define NCLS    9
#define PRE_K   512
#define DETS    100
#define IMGW    640.0f
#define IMGH    384.0f

#define O_EMB   ((size_t)0)
#define O_CLS   ((size_t)51380224)
#define O_REG   ((size_t)51389440)
#define O_BOX   ((size_t)51426304)
#define O_SCO   ((size_t)51427104)
#define O_LAB   ((size_t)51427304)
#define O_VAL   ((size_t)51427504)

// packed-M GEMM geometry: 1024 samples x 50 rows (49 valid + 1 pad), 400 m-tiles
#define MTILES 400

// tile-contiguous A/B blocks (image the smem stage layout, pads included)
#define A_TILE_W 4352u          // words per A tile (64 rows x 68 words, 272B rows)
#define B_TILE_H 9216u          // halves per B tile (128 rows x 72 halves, 144B rows)

// ---------------- scratch (device globals; no allocation) ----------------
#define XN ((size_t)1024*512*56)
#define HN ((size_t)1024*1024*56)
__device__ __align__(16) __half g_x16r [XN + 128];
__device__ __align__(16) __half g_x16lr[XN + 128];
__device__ __align__(16) __half g_x16sr[XN + 128];     // shifted by +1 half
__device__ __align__(16) __half g_x16lsr[XN + 128];
__device__ __align__(16) __half g_h16r [HN + 128];
__device__ __align__(16) __half g_h16lr[HN + 128];
__device__ __align__(16) __half g_h16sr[HN + 128];
__device__ __align__(16) __half g_h16lsr[HN + 128];
#define X16  (g_x16r  + 64)
#define X16L (g_x16lr + 64)
#define X16S (g_x16sr + 64)
#define X16LS (g_x16lsr + 64)
#define H16  (g_h16r  + 64)
#define H16L (g_h16lr + 64)
#define H16S (g_h16sr + 64)
#define H16LS (g_h16lsr + 64)

// A^T im2col, tiled: tile (kc, mt) at ((kc*400+mt) * 4352) words
__device__ __align__(16) __half g_A1h[(size_t)72 *MTILES*2*A_TILE_W];
__device__ __align__(16) __half g_A1l[(size_t)72 *MTILES*2*A_TILE_W];
__device__ __align__(16) __half g_A2h[(size_t)152*MTILES*2*A_TILE_W];
__device__ __align__(16) __half g_A2l[(size_t)152*MTILES*2*A_TILE_W];

// B weights, tiled: tile (kc, nt) at ((kc*8+nt) * 9216) halves
__device__ __align__(16) __half g_w1h[(size_t)72 *8*B_TILE_H];
__device__ __align__(16) __half g_w1l[(size_t)72 *8*B_TILE_H];
__device__ __align__(16) __half g_wbh[(size_t)152*8*B_TILE_H];
__device__ __align__(16) __half g_wbl[(size_t)152*8*B_TILE_H];

__device__ uint32_t g_mask[9][25];

__device__ float g_flat[(size_t)NSAMP*1024];
__device__ float g_cls[NSAMP*NCLS];
__device__ float g_reg[NSAMP*NCLS*4];
__device__ float g_boxes[NSAMP*NCLS*4];
__device__ float g_scores[NSAMP*NCLS];

// ================= PTX helpers =================
__device__ __forceinline__ uint32_t smem_u32(const void* p) {
    uint32_t a;
    asm("{ .reg .u64 t; cvta.to.shared.u64 t, %1; cvt.u32.u64 %0, t; }" : "=r"(a) : "l"(p));
    return a;
}
// 1D TMA bulk copy global->shared with mbarrier completion (sm_90+ generic PTX)
__device__ __forceinline__ void cp_bulk(uint32_t dst, const void* src, uint32_t bytes,
                                        uint32_t mbar) {
    asm volatile(
        "cp.async.bulk.shared::cluster.global.mbarrier::complete_tx::bytes [%0], [%1], %2, [%3];"
        :: "r"(dst), "l"(src), "r"(bytes), "r"(mbar) : "memory");
}
#define MBAR_INIT(mb, n) asm volatile("mbarrier.init.shared.b64 [%0], %1;" :: "r"(mb), "r"(n) : "memory")
#define MBAR_EXPECT(mb, tx) asm volatile("mbarrier.arrive.expect_tx.shared.b64 _, [%0], %1;" :: "r"(mb), "r"(tx) : "memory")
#define FENCE_ASYNC() asm volatile("fence.proxy.async.shared::cta;" ::: "memory")
__device__ __forceinline__ void mbar_wait(uint32_t mb, uint32_t parity) {
    asm volatile(
        "{\n\t.reg .pred P;\n\t"
        "W%=:\n\tmbarrier.try_wait.parity.acquire.cta.shared::cta.b64 P, [%0], %1, 0x989680;\n\t"
        "@!P bra W%=;\n\t}"
        :: "r"(mb), "r"(parity) : "memory");
}

__device__ __forceinline__ void ldm_x4(uint32_t* r, uint32_t a) {
    asm volatile("ldmatrix.sync.aligned.m8n8.x4.shared.b16 {%0,%1,%2,%3}, [%4];"
        : "=r"(r[0]), "=r"(r[1]), "=r"(r[2]), "=r"(r[3]) : "r"(a));
}
__device__ __forceinline__ void ldm_x4t(uint32_t* r, uint32_t a) {
    asm volatile("ldmatrix.sync.aligned.m8n8.x4.trans.shared.b16 {%0,%1,%2,%3}, [%4];"
        : "=r"(r[0]), "=r"(r[1]), "=r"(r[2]), "=r"(r[3]) : "r"(a));
}
__device__ __forceinline__ void mma16816(float* c, const uint32_t* a, uint32_t b0, uint32_t b1) {
    asm volatile(
        "mma.sync.aligned.m16n8k16.row.col.f32.f16.f16.f32 "
        "{%0,%1,%2,%3}, {%4,%5,%6,%7}, {%8,%9}, {%0,%1,%2,%3};"
        : "+f"(c[0]), "+f"(c[1]), "+f"(c[2]), "+f"(c[3])
        : "r"(a[0]), "r"(a[1]), "r"(a[2]), "r"(a[3]), "r"(b0), "r"(b1));
}

// ---------------- conversion / prep kernels ----------------
__global__ void cvt_x16(const float* __restrict__ x) {
    size_t i = (size_t)blockIdx.x * 256 + threadIdx.x;
    if (i >= XN) return;
    int p = (int)(i % 56);
    size_t row = i / 56;
    float v = (p < 49) ? x[row * 49 + p] : 0.f;
    __half hh = __float2half(v);
    X16[i]  = hh;
    X16L[i] = __float2half(v - __half2float(hh));
}
__global__ void shift_x() {
    size_t i = (size_t)blockIdx.x * 256 + threadIdx.x;
    if (i >= XN) return;
    X16S[i]  = X16[i + 1];
    X16LS[i] = X16L[i + 1];
}
__global__ void shift_h() {
    size_t i = (size_t)blockIdx.x * 256 + threadIdx.x;
    if (i >= HN) return;
    H16S[i]  = H16[i + 1];
    H16LS[i] = H16L[i + 1];
}
// weights -> tiled [kc][co 128 x 72 halves]
__global__ void cvt_w1h(const float* __restrict__ w) {
    size_t i = (size_t)blockIdx.x * 256 + threadIdx.x;
    if (i >= (size_t)1024*4608) return;
    int co = (int)(i / 4608);
    int kk = (int)(i - (size_t)co * 4608);
    float v = w[i];
    __half hh = __float2half(v);
    size_t d = (size_t)((kk >> 6) * 8 + (co >> 7)) * B_TILE_H + (co & 127) * 72 + (kk & 63);
    g_w1h[d] = hh;
    g_w1l[d] = __float2half(v - __half2float(hh));
}
__global__ void cvt_wbh(const float* __restrict__ w2, const float* __restrict__ wd) {
    size_t i = (size_t)blockIdx.x * 256 + threadIdx.x;
    if (i >= (size_t)1024*9728) return;
    int co = (int)(i / 9728);
    int kk = (int)(i - (size_t)co * 9728);
    float v = (kk < 9216) ? w2[(size_t)co * 9216 + kk] : wd[(size_t)co * 512 + (kk - 9216)];
    __half hh = __float2half(v);
    size_t d = (size_t)((kk >> 6) * 8 + (co >> 7)) * B_TILE_H + (co & 127) * 72 + (kk & 63);
    g_wbh[d] = hh;
    g_wbl[d] = __float2half(v - __half2float(hh));
}
__global__ void init_mask() {
    int t = threadIdx.x;
    if (t >= 225) return;
    int off = t / 25, w = t - (t / 25) * 25;
    int ky = off / 3, kx = off - (off / 3) * 3;
    uint32_t m = 0;
    #pragma unroll
    for (int h = 0; h < 2; h++) {
        int p = 2 * w + h;
        if (p < 49) {
            int y = p / 7, x = p - (p / 7) * 7;
            int yy = y + ky - 1, xx = x + kx - 1;
            if (yy >= 0 && yy < 7 && xx >= 0 && xx < 7) m |= 0xFFFFu << (16 * h);
        }
    }
    g_mask[off][w] = m;
}

// ---------------- im2col to tiled global A^T (hi + lo) ----------------
template<int P>
__global__ void im2col_kernel() {
    int idx = blockIdx.x * 256 + threadIdx.x;
    int n  = idx & 1023;
    int kk = idx >> 10;
    const int KK = (P == 1) ? 4608 : 9728;
    if (kk >= KK) return;

    int ci, off;
    const __half *H, *Hs, *L, *Ls;
    int CI;
    if (P == 2 && kk >= 9216) {
        ci = kk - 9216; off = 4;                 // center tap, del = 0
        H = X16; Hs = X16S; L = X16L; Ls = X16LS; CI = 512;
    } else {
        ci = kk / 9; off = kk - ci * 9;
        if (P == 1) { H = X16; Hs = X16S; L = X16L; Ls = X16LS; CI = 512; }
        else        { H = H16; Hs = H16S; L = H16L; Ls = H16LS; CI = 1024; }
    }
    int ky = off / 3, kx = off - ky * 3;
    int del = (ky - 1) * 7 + (kx - 1);
    int sh  = del & 1;
    int ws  = (del - sh) >> 1;

    const uint32_t* src  = (const uint32_t*)((sh ? Hs : H) + (size_t)(n * CI + ci) * 56) + ws;
    const uint32_t* srcL = (const uint32_t*)((sh ? Ls : L) + (size_t)(n * CI + ci) * 56) + ws;
    uint32_t* dh_b = (uint32_t*)((P == 1) ? g_A1h : g_A2h);
    uint32_t* dl_b = (uint32_t*)((P == 1) ? g_A1l : g_A2l);
    const uint32_t* mk = g_mask[off];

    size_t base = (size_t)(kk >> 6) * MTILES * A_TILE_W + (size_t)(kk & 63) * 68;
    int m0 = n * 50;
    #pragma unroll
    for (int w = 0; w < 25; w++) {
        int m = m0 + 2 * w;
        size_t d = base + (size_t)(m >> 7) * A_TILE_W + ((m & 127) >> 1);
        uint32_t mm = mk[w];
        dh_b[d] = src[w]  & mm;
        dl_b[d] = srcL[w] & mm;
    }
}

// ---------------- pure split-fp16 GEMM (3 products, fp32 acc), TMA-fed ----------------
// smem: Ah/Al [3][64 kk][136 h] (272B rows), Bh/Bl [3][128 co][72 h] (144B rows)
#define AST2 272u
#define BST2 144u
#define A_SZ 17408u
#define B_SZ 18432u
#define AHO(st) ((uint32_t)(st) * A_SZ)
#define ALO(st) (52224u + (uint32_t)(st) * A_SZ)
#define BHO(st) (104448u + (uint32_t)(st) * B_SZ)
#define BLO(st) (159744u + (uint32_t)(st) * B_SZ)
#define MB_OFF  215040u
#define GSMEM   215072
#define CHUNK_TX (2u * A_SZ + 2u * B_SZ)       // 71680

__device__ __forceinline__ void mma8(float (*acc)[4], const uint32_t A[2][4],
                                     const uint32_t Q0[4], const uint32_t Q1[4]) {
    #pragma unroll
    for (int i = 0; i < 2; i++) {
        mma16816(acc[i*4+0], A[i], Q0[0], Q0[2]);
        mma16816(acc[i*4+1], A[i], Q0[1], Q0[3]);
        mma16816(acc[i*4+2], A[i], Q1[0], Q1[2]);
        mma16816(acc[i*4+3], A[i], Q1[1], Q1[3]);
    }
}

template<int P>
__global__ void __launch_bounds__(512, 1) gemm_conv(float* __restrict__ d_out) {
    extern __shared__ char smem[];
    const uint32_t sb = smem_u32(smem);
    const int tid  = threadIdx.x;
    const int lane = tid & 31;
    const int wid  = tid >> 5;                 // 16 warps
    const int wm   = wid >> 2, wn = wid & 3;   // 4x4 warp grid, 32x32 tiles
    const int nt   = blockIdx.x;               // 8 n-tiles
    const int mt   = blockIdx.y;               // 400 m-tiles

    const char* Ah_g = (const char*)((P == 1) ? g_A1h : g_A2h);
    const char* Al_g = (const char*)((P == 1) ? g_A1l : g_A2l);
    const char* Wh_g = (const char*)((P == 1) ? g_w1h : g_wbh);
    const char* Wl_g = (const char*)((P == 1) ? g_w1l : g_wbl);
    const int NC = (P == 1) ? 72 : 152;

    if (tid == 0) {
        MBAR_INIT(sb + MB_OFF + 0, 1);
        MBAR_INIT(sb + MB_OFF + 8, 1);
        MBAR_INIT(sb + MB_OFF + 16, 1);
        FENCE_ASYNC();
    }
    __syncthreads();

    auto issue = [&](int c) {
        if (c < NC && tid == 0) {
            int st = c - (c / 3) * 3;
            uint32_t mb = sb + MB_OFF + (uint32_t)st * 8u;
            MBAR_EXPECT(mb, CHUNK_TX);
            size_t at = ((size_t)c * MTILES + mt) * A_SZ;
            size_t bt = ((size_t)c * 8 + nt) * B_SZ;
            cp_bulk(sb + AHO(st), Ah_g + at, A_SZ, mb);
            cp_bulk(sb + ALO(st), Al_g + at, A_SZ, mb);
            cp_bulk(sb + BHO(st), Wh_g + bt, B_SZ, mb);
            cp_bulk(sb + BLO(st), Wl_g + bt, B_SZ, mb);
        }
    };

    float acc[8][4];
    #pragma unroll
    for (int i = 0; i < 8; i++)
        #pragma unroll
        for (int e = 0; e < 4; e++) acc[i][e] = 0.f;

    const uint32_t aRow = ((lane & 7) + ((lane >> 4) & 1) * 8) * AST2
                        + (uint32_t)(wm * 32 + ((lane >> 3) & 1) * 8) * 2u;
    const uint32_t bRow = (uint32_t)(wn * 32 + (lane & 15)) * BST2 + ((lane >> 4) & 1) * 16u;

    issue(0); issue(1);

    for (int c = 0; c < NC; c++) {
        int st = c - (c / 3) * 3;
        mbar_wait(sb + MB_OFF + (uint32_t)st * 8u, (uint32_t)((c / 3) & 1));
        __syncthreads();                       // stage (c-1)%3 fully consumed by all
        issue(c + 2);                          // refill stage (c+2)%3 == (c-1)%3
        const uint32_t Ahs = sb + AHO(st), Als = sb + ALO(st);
        const uint32_t Bhs = sb + BHO(st), Bls = sb + BLO(st);
        #pragma unroll
        for (int ks = 0; ks < 4; ks++) {
            uint32_t A[2][4], AL[2][4], Q0[4], Q1[4], R0[4], R1[4];
            const uint32_t ao = aRow + (uint32_t)ks * (16u * AST2);
            const uint32_t bo = bRow + (uint32_t)ks * 32u;
            ldm_x4t(A[0],  Ahs + ao);
            ldm_x4t(A[1],  Ahs + ao + 32u);
            ldm_x4t(AL[0], Als + ao);
            ldm_x4t(AL[1], Als + ao + 32u);
            ldm_x4(Q0, Bhs + bo);
            ldm_x4(Q1, Bhs + bo + 16u * BST2);
            ldm_x4(R0, Bls + bo);
            ldm_x4(R1, Bls + bo + 16u * BST2);
            mma8(&acc[0], A,  Q0, Q1);         // Ah*Bh
            mma8(&acc[0], AL, Q0, Q1);         // Al*Bh
            mma8(&acc[0], A,  R0, R1);         // Ah*Bl
        }
    }
    __syncthreads();

    // ---- epilogue: stage through smem [128 co][132 m] floats, relu ----
    float* sf = (float*)smem;
    #pragma unroll
    for (int i = 0; i < 2; i++) {
        #pragma unroll
        for (int j = 0; j < 4; j++) {
            int m  = wm * 32 + i * 16 + (lane >> 2);
            int co = wn * 32 + j * 8 + ((lane & 3) << 1);
            const float* a = acc[i*4+j];
            sf[co * 132 + m]           = fmaxf(a[0], 0.f);
            sf[(co + 1) * 132 + m]     = fmaxf(a[1], 0.f);
            sf[co * 132 + m + 8]       = fmaxf(a[2], 0.f);
            sf[(co + 1) * 132 + m + 8] = fmaxf(a[3], 0.f);
        }
    }
    __syncthreads();
    for (int idx = tid; idx < 128 * 128; idx += 512) {
        int co_l = idx >> 7, ml = idx & 127;
        int m_g = mt * 128 + ml;
        int n = m_g / 50;
        int p = m_g - n * 50;
        if (p < 49) {
            float v = sf[co_l * 132 + ml];
            int co_g = nt * 128 + co_l;
            if (P == 1) {
                size_t o = ((size_t)(n * 1024 + co_g)) * 56 + p;
                __half hh = __float2half(v);
                H16[o]  = hh;
                H16L[o] = __float2half(v - __half2float(hh));
            } else {
                d_out[O_EMB + ((size_t)(n * 1024 + co_g)) * 49 + p] = v;
            }
        }
    }
}

// ---------------- avg pool ----------------
__global__ void flat_kernel(const float* __restrict__ emb) {
    int n = blockIdx.x;
    for (int co = threadIdx.x; co < 1024; co += 256) {
        const float* e = emb + ((size_t)n * 1024 + co) * 49;
        float s = 0.f;
        #pragma unroll
        for (int p = 0; p < 49; p++) s += e[p];
        g_flat[(size_t)n * 1024 + co] = s / 49.0f;
    }
}

// ---------------- head GEMMs ----------------
__global__ void head_kernel(const float* __restrict__ cls_w, const float* __restrict__ cls_b,
                            const float* __restrict__ reg_w, const float* __restrict__ reg_b,
                            float* __restrict__ d_out) {
    int n = blockIdx.x;
    int w = threadIdx.x >> 5, lane = threadIdx.x & 31;
    const float* f = g_flat + (size_t)n * 1024;
    for (int o = w; o < 45; o += 8) {
        const float* wr; float bias;
        if (o < NCLS) { wr = cls_w + (size_t)o * 1024; bias = cls_b[o]; }
        else          { wr = reg_w + (size_t)(o - NCLS) * 1024; bias = reg_b[o - NCLS]; }
        float acc = 0.f;
        for (int k = lane; k < 1024; k += 32) acc += f[k] * wr[k];
        #pragma unroll
        for (int d = 16; d; d >>= 1) acc += __shfl_xor_sync(0xffffffffu, acc, d);
        if (lane == 0) {
            float v = acc + bias;
            if (o < NCLS) { g_cls[n * NCLS + o] = v; d_out[O_CLS + n * NCLS + o] = v; }
            else { g_reg[n * 36 + (o - NCLS)] = v; d_out[O_REG + n * 36 + (o - NCLS)] = v; }
        }
    }
}

// ---------------- softmax + box decode + clip ----------------
__global__ void decode_kernel(const float* __restrict__ proposals) {
    int n = blockIdx.x; int lane = threadIdx.x;
    float logit = (lane < NCLS) ? g_cls[n * NCLS + lane] : -INFINITY;
    float m = logit;
    #pragma unroll
    for (int d = 16; d; d >>= 1) m = fmaxf(m, __shfl_xor_sync(0xffffffffu, m, d));
    float e = (lane < NCLS) ? expf(logit - m) : 0.f;
    float s = e;
    #pragma unroll
    for (int d = 16; d; d >>= 1) s += __shfl_xor_sync(0xffffffffu, s, d);
    if (lane < NCLS) {
        g_scores[n * NCLS + lane] = e / s;
        const float* pr = proposals + (size_t)n * 4;
        float pw = pr[2] - pr[0], ph = pr[3] - pr[1];
        float pcx = pr[0] + 0.5f * pw, pcy = pr[1] + 0.5f * ph;
        const float* rr = g_reg + n * 36 + lane * 4;
        float dx = rr[0] / 10.0f, dy = rr[1] / 10.0f;
        float dw = fminf(rr[2] / 5.0f, 4.135166556742356f);
        float dh = fminf(rr[3] / 5.0f, 4.135166556742356f);
        float ncx = dx * pw + pcx, ncy = dy * ph + pcy;
        float nw = expf(dw) * pw, nh = expf(dh) * ph;
        float b0 = fminf(fmaxf(ncx - 0.5f * nw, 0.f), IMGW);
        float b1 = fminf(fmaxf(ncy - 0.5f * nh, 0.f), IMGH);
        float b2 = fminf(fmaxf(ncx + 0.5f * nw, 0.f), IMGW);
        float b3 = fminf(fmaxf(ncy + 0.5f * nh, 0.f), IMGH);
        float* bp = g_boxes + (size_t)(n * NCLS + lane) * 4;
        bp[0] = b0; bp[1] = b1; bp[2] = b2; bp[3] = b3;
    }
}

// ---------------- per-image: filter -> sort(4096) -> NMS(512) -> top-100 ----------------
__global__ void __launch_bounds__(512) nms_kernel(float* __restrict__ d_out) {
    __shared__ float skey[4096];
    __shared__ int   sidx[4096];
    __shared__ float sbox[PRE_K * 4];
    __shared__ int   skeep[PRE_K];
    __shared__ int   swsum[16];

    int img = blockIdx.x; int tid = threadIdx.x;

    for (int j = tid; j < 4096; j += 512) {
        int p = j >> 3, c = (j & 7) + 1;
        int n = img * 512 + p;
        float s = g_scores[n * NCLS + c];
        const float* bb = g_boxes + (size_t)(n * NCLS + c) * 4;
        bool valid = (s > 0.05f) && ((bb[2] - bb[0]) >= 0.01f) && ((bb[3] - bb[1]) >= 0.01f);
        skey[j] = valid ? s : -INFINITY;
        sidx[j] = j;
    }
    __syncthreads();

    for (int k = 2; k <= 4096; k <<= 1) {
        for (int j2 = k >> 1; j2 > 0; j2 >>= 1) {
            for (int i = tid; i < 4096; i += 512) {
                int ixj = i ^ j2;
                if (ixj > i) {
                    float ka = skey[i], kb = skey[ixj];
                    int ia = sidx[i], ib = sidx[ixj];
                    bool a_first = (ka > kb) || (ka == kb && ia < ib);
                    bool up = ((i & k) == 0);
                    if (up ? !a_first : a_first) {
                        skey[i] = kb; skey[ixj] = ka;
                        sidx[i] = ib; sidx[ixj] = ia;
                    }
                }
            }
            __syncthreads();
        }
    }

    if (tid < PRE_K) {
        float s = skey[tid];
        int j = sidx[tid];
        int p = j >> 3, c = (j & 7) + 1;
        int n = img * 512 + p;
        const float* bb = g_boxes + (size_t)(n * NCLS + c) * 4;
        float off = 641.0f * (float)c;
        sbox[tid * 4 + 0] = bb[0] + off;
        sbox[tid * 4 + 1] = bb[1] + off;
        sbox[tid * 4 + 2] = bb[2] + off;
        sbox[tid * 4 + 3] = bb[3] + off;
        skeep[tid] = (s != -INFINITY) ? 1 : 0;
    }
    __syncthreads();

    for (int i = 0; i < PRE_K; i++) {
        if (skeep[i]) {
            int j = tid;
            if (j > i && skeep[j]) {
                float ax0 = sbox[i*4], ay0 = sbox[i*4+1], ax1 = sbox[i*4+2], ay1 = sbox[i*4+3];
                float bx0 = sbox[j*4], by0 = sbox[j*4+1], bx1 = sbox[j*4+2], by1 = sbox[j*4+3];
                float areaA = (ax1 - ax0) * (ay1 - ay0);
                float areaB = (bx1 - bx0) * (by1 - by0);
                float iw = fmaxf(fminf(ax1, bx1) - fmaxf(ax0, bx0), 0.f);
                float ih = fmaxf(fminf(ay1, by1) - fmaxf(ay0, by0), 0.f);
                float inter = iw * ih;
                float iou = inter / fmaxf(areaA + areaB - inter, 1e-8f);
                if (iou > 0.5f) skeep[j] = 0;
            }
        }
        __syncthreads();
    }

    int keepflag = (tid < PRE_K) ? skeep[tid] : 0;
    unsigned mask = __ballot_sync(0xffffffffu, keepflag != 0);
    int lane = tid & 31, wid = tid >> 5;
    if (lane == 0) swsum[wid] = __popc(mask);
    __syncthreads();
    int base = 0;
    for (int w = 0; w < wid; w++) base += swsum[w];
    int rank = base + __popc(mask & ((1u << lane) - 1u));

    float* dbx = d_out + O_BOX + (size_t)img * DETS * 4;
    float* dsc = d_out + O_SCO + (size_t)img * DETS;
    float* dlb = d_out + O_LAB + (size_t)img * DETS;
    float* dvl = d_out + O_VAL + (size_t)img * DETS;
    for (int i = tid; i < DETS; i += 512) {
        dbx[i*4+0] = 0.f; dbx[i*4+1] = 0.f; dbx[i*4+2] = 0.f; dbx[i*4+3] = 0.f;
        dsc[i] = 0.f; dlb[i] = 0.f; dvl[i] = 0.f;
    }
    __syncthreads();
    if (keepflag && rank < DETS) {
        int j = sidx[tid];
        int p = j >> 3, c = (j & 7) + 1;
        int n = img * 512 + p;
        const float* bb = g_boxes + (size_t)(n * NCLS + c) * 4;
        dbx[rank*4+0] = bb[0]; dbx[rank*4+1] = bb[1];
        dbx[rank*4+2] = bb[2]; dbx[rank*4+3] = bb[3];
        dsc[rank] = skey[tid];
        dlb[rank] = (float)c;
        dvl[rank] = 1.0f;
    }
}

// ---------------- launch ----------------
extern "C" void kernel_launch(void* const* d_in, const int* in_sizes, int n_in,
                              void* d_out, int out_size) {
    const float* feats     = (const float*)d_in[0];
    const float* proposals = (const float*)d_in[1];
    const float* w1        = (const float*)d_in[2];
    const float* w2        = (const float*)d_in[3];
    const float* wd        = (const float*)d_in[4];
    const float* cls_w     = (const float*)d_in[5];
    const float* cls_b     = (const float*)d_in[6];
    const float* reg_w     = (const float*)d_in[7];
    const float* reg_b     = (const float*)d_in[8];
    float* out = (float*)d_out;

    cudaFuncSetAttribute(gemm_conv<1>, cudaFuncAttributeMaxDynamicSharedMemorySize, GSMEM);
    cudaFuncSetAttribute(gemm_conv<2>, cudaFuncAttributeMaxDynamicSharedMemorySize, GSMEM);

    cvt_x16<<<(int)((XN + 255) / 256), 256>>>(feats);
    shift_x<<<(int)((XN + 255) / 256), 256>>>();
    cvt_w1h<<<(int)(((size_t)1024*4608 + 255) / 256), 256>>>(w1);
    cvt_wbh<<<(int)(((size_t)1024*9728 + 255) / 256), 256>>>(w2, wd);
    init_mask<<<1, 256>>>();

    im2col_kernel<1><<<4608 * 4, 256>>>();
    gemm_conv<1><<<dim3(8, 400), 512, GSMEM>>>(out);

    shift_h<<<(int)((HN + 255) / 256), 256>>>();
    im2col_kernel<2><<<9728 * 4, 256>>>();
    gemm_conv<2><<<dim3(8, 400), 512, GSMEM>>>(out);

    flat_kernel<<<NSAMP, 256>>>(out + O_EMB);
    head_kernel<<<NSAMP, 256>>>(cls_w, cls_b, reg_w, reg_b, out);
    decode_kernel<<<NSAMP, 32>>>(proposals);
    nms_kernel<<<2, 512>>>(out);
}